// round 10
// baseline (speedup 1.0000x reference)
#include <cuda_runtime.h>

#define NN   100000
#define EE   1600000
#define DIM  128
#define OUTD 64
#define NB_SCAN 196      // ceil(NN/512)
#define GEMM_BLKS 782    // ceil(NN/128)
#define FUSE_STRIDE 17   // 1 gemm block per 16 pull blocks
#define FUSE_GRID (GEMM_BLKS * FUSE_STRIDE)   // 13294

// ---------------- scratch (device globals; no allocation allowed) ----------
__device__ float g_dinv[NN];
__device__ int   g_cnt[NN];
__device__ int   g_off[NN + 1];
__device__ int   g_cur[NN];
__device__ int   g_bsum[256];
__device__ int2  g_adj[EE];                  // (src_row, scale_as_float_bits)
__device__ float g_acc0[(size_t)NN * DIM];
__device__ float g_acc1[(size_t)NN * DIM];
__device__ float g_bufA[(size_t)NN * DIM];
__device__ float g_bufB[(size_t)NN * DIM];

__device__ __forceinline__ float lo32(unsigned long long u) {
    return __uint_as_float((unsigned)u);
}
__device__ __forceinline__ float hi32(unsigned long long u) {
    return __uint_as_float((unsigned)(u >> 32));
}

// ---------------- degree -----------------------------------------------------
__global__ void k_deg_init() {
    int i = blockIdx.x * blockDim.x + threadIdx.x;
    if (i < NN) g_cnt[i] = 0;
}
__global__ void k_deg_count(const int* __restrict__ ei) {
    int i = blockIdx.x * blockDim.x + threadIdx.x;
    if (i < EE) atomicAdd(&g_cnt[ei[EE + i]], 1);
}
__global__ void k_deg_fin() {
    int i = blockIdx.x * blockDim.x + threadIdx.x;
    if (i < NN) g_dinv[i] = rsqrtf((float)g_cnt[i] + 1.0f);   // +1 self loop
}

// ---------------- exclusive scan of g_cnt -> g_off ---------------------------
__global__ void k_scan1() {               // 512 threads per block
    __shared__ int s[512];
    int t = threadIdx.x;
    int i = blockIdx.x * 512 + t;
    int v = (i < NN) ? g_cnt[i] : 0;
    s[t] = v;
    __syncthreads();
#pragma unroll
    for (int off = 1; off < 512; off <<= 1) {
        int u = (t >= off) ? s[t - off] : 0;
        __syncthreads();
        s[t] += u;
        __syncthreads();
    }
    if (i < NN) { g_off[i] = s[t] - v; g_cur[i] = 0; }
    if (t == 511) g_bsum[blockIdx.x] = s[511];
}
__global__ void k_scan2() {               // 1 block, 256 threads
    __shared__ int s[256];
    int t = threadIdx.x;
    int v = (t < NB_SCAN) ? g_bsum[t] : 0;
    s[t] = v;
    __syncthreads();
#pragma unroll
    for (int off = 1; off < 256; off <<= 1) {
        int u = (t >= off) ? s[t - off] : 0;
        __syncthreads();
        s[t] += u;
        __syncthreads();
    }
    if (t < NB_SCAN) g_bsum[t] = s[t] - v;
}
__global__ void k_scan3() {
    int i = blockIdx.x * blockDim.x + threadIdx.x;
    if (i < NN) g_off[i] += g_bsum[i >> 9];
    if (i == 0) g_off[NN] = EE;
}

// ---------------- CSR fill ---------------------------------------------------
__global__ void k_fill(const int* __restrict__ ei) {
    int i = blockIdx.x * blockDim.x + threadIdx.x;
    if (i >= EE) return;
    int r = ei[i];
    int c = ei[EE + i];
    int pos = g_off[c] + atomicAdd(&g_cur[c], 1);
    float s = g_dinv[r] * g_dinv[c];
    g_adj[pos] = make_int2(r, __float_as_int(s));
}

// ---------------- device bodies ---------------------------------------------
// pull: one warp per node, self-loop fused
__device__ __forceinline__ void pull_body(const float* __restrict__ src,
                                          float* __restrict__ dst,
                                          int pblk) {
    int w = pblk * 8 + ((int)threadIdx.x >> 5);
    if (w >= NN) return;
    int lane = threadIdx.x & 31;
    int beg = g_off[w];
    int end = g_off[w + 1];
    float d = g_dinv[w];
    float dd = d * d;
    float4 acc = ((const float4*)(src + (size_t)w * DIM))[lane];
    acc.x *= dd; acc.y *= dd; acc.z *= dd; acc.w *= dd;
#pragma unroll 4
    for (int j = beg; j < end; j++) {
        int2 e = __ldg(&g_adj[j]);
        float s = __int_as_float(e.y);
        float4 v = ((const float4*)(src + (size_t)e.x * DIM))[lane];
        acc.x += s * v.x; acc.y += s * v.y;
        acc.z += s * v.z; acc.w += s * v.w;
    }
    ((float4*)(dst + (size_t)w * DIM))[lane] = acc;
}

// GEMM (FFMA2): C[128-tile][128] (+)= A[*][128]*B[128][128]
// BM=128, BN=128, BK=32, 256 threads, TM=8, TN=8 (4 packed f32x2 pairs)
__device__ __forceinline__ void gemm_body(const float* __restrict__ A,
                                          const float* __restrict__ B,
                                          float* __restrict__ C,
                                          const float* __restrict__ bias,
                                          int gblk) {
    __shared__ float AsD[32][256];   // 32 KB, A[m][k] duplicated pairs
    __shared__ float Bs [32][128];   // 16 KB
    int tid = threadIdx.x;
    int tx  = tid & 15;              // cols tx*8 .. tx*8+7
    int ty  = tid >> 4;              // rows ty*8 .. ty*8+7
    int m0  = gblk * 128;

    unsigned long long acc[8][4];
#pragma unroll
    for (int m = 0; m < 8; m++)
#pragma unroll
        for (int p = 0; p < 4; p++) acc[m][p] = 0ull;

    for (int k0 = 0; k0 < DIM; k0 += 32) {
#pragma unroll
        for (int l = 0; l < 4; l++) {
            int f  = tid + l * 256;
            int r  = f & 127;
            int kv = f >> 7;
            float4 v = make_float4(0.f, 0.f, 0.f, 0.f);
            int gr = m0 + r;
            if (gr < NN) v = *(const float4*)(A + (size_t)gr * DIM + k0 + kv * 4);
            *(float2*)&AsD[kv * 4 + 0][2 * r] = make_float2(v.x, v.x);
            *(float2*)&AsD[kv * 4 + 1][2 * r] = make_float2(v.y, v.y);
            *(float2*)&AsD[kv * 4 + 2][2 * r] = make_float2(v.z, v.z);
            *(float2*)&AsD[kv * 4 + 3][2 * r] = make_float2(v.w, v.w);
        }
#pragma unroll
        for (int l = 0; l < 4; l++) {
            int f  = tid + l * 256;
            int k  = f >> 5;
            int cv = f & 31;
            *(float4*)&Bs[k][cv * 4] = *(const float4*)(B + (size_t)(k0 + k) * DIM + cv * 4);
        }
        __syncthreads();

#pragma unroll
        for (int k = 0; k < 32; k++) {
            ulonglong2 a01 = *(const ulonglong2*)&AsD[k][ty * 16 + 0];
            ulonglong2 a23 = *(const ulonglong2*)&AsD[k][ty * 16 + 4];
            ulonglong2 a45 = *(const ulonglong2*)&AsD[k][ty * 16 + 8];
            ulonglong2 a67 = *(const ulonglong2*)&AsD[k][ty * 16 + 12];
            ulonglong2 b01 = *(const ulonglong2*)&Bs[k][tx * 8 + 0];
            ulonglong2 b23 = *(const ulonglong2*)&Bs[k][tx * 8 + 4];
            unsigned long long av[8] = {a01.x, a01.y, a23.x, a23.y,
                                        a45.x, a45.y, a67.x, a67.y};
            unsigned long long bv[4] = {b01.x, b01.y, b23.x, b23.y};
#pragma unroll
            for (int m = 0; m < 8; m++)
#pragma unroll
                for (int p = 0; p < 4; p++)
                    asm("fma.rn.f32x2 %0, %1, %2, %0;"
                        : "+l"(acc[m][p]) : "l"(av[m]), "l"(bv[p]));
        }
        __syncthreads();
    }

    float bsum[8];
    if (bias) {
#pragma unroll
        for (int j = 0; j < 8; j++) {
            int c = tx * 8 + j;
            bsum[j] = bias[c] + bias[DIM + c] + bias[2 * DIM + c]
                    + bias[3 * DIM + c] + bias[4 * DIM + c];
        }
    }
#pragma unroll
    for (int m = 0; m < 8; m++) {
        int gr = m0 + ty * 8 + m;
        if (gr >= NN) continue;
        float* row = C + (size_t)gr * DIM + tx * 8;
        float r0 = lo32(acc[m][0]), r1 = hi32(acc[m][0]);
        float r2 = lo32(acc[m][1]), r3 = hi32(acc[m][1]);
        float r4 = lo32(acc[m][2]), r5 = hi32(acc[m][2]);
        float r6 = lo32(acc[m][3]), r7 = hi32(acc[m][3]);
        if (bias) {
            r0 += bsum[0]; r1 += bsum[1]; r2 += bsum[2]; r3 += bsum[3];
            r4 += bsum[4]; r5 += bsum[5]; r6 += bsum[6]; r7 += bsum[7];
        } else {
            float4 c0 = *(float4*)(row);
            float4 c1 = *(float4*)(row + 4);
            r0 += c0.x; r1 += c0.y; r2 += c0.z; r3 += c0.w;
            r4 += c1.x; r5 += c1.y; r6 += c1.z; r7 += c1.w;
        }
        *(float4*)(row)     = make_float4(r0, r1, r2, r3);
        *(float4*)(row + 4) = make_float4(r4, r5, r6, r7);
    }
}

// ---------------- fused launch: gemm(Ag) + pull(psrc->pdst) ------------------
// blockIdx % 17 == 0 -> gemm tile (blockIdx/17); else pull block.
__global__ void __launch_bounds__(256, 2) k_fused(const float* __restrict__ Ag,
                                                  const float* __restrict__ B,
                                                  float* __restrict__ C,
                                                  const float* __restrict__ bias,
                                                  const float* __restrict__ psrc,
                                                  float* __restrict__ pdst) {
    int bx = blockIdx.x;
    int q  = bx / FUSE_STRIDE;
    if (bx == q * FUSE_STRIDE) {
        gemm_body(Ag, B, C, bias, q);
    } else {
        pull_body(psrc, pdst, bx - q - 1);   // pull blocks before bx = bx - (q+1)
    }
}

// ---------------- pure gemm launch ------------------------------------------
__global__ void __launch_bounds__(256, 2) k_gemm(const float* __restrict__ A,
                                                 const float* __restrict__ B,
                                                 float* __restrict__ C,
                                                 const float* __restrict__ bias) {
    gemm_body(A, B, C, bias, blockIdx.x);
}

// ---------------- fusion + classifier (FFMA2) --------------------------------
// out = (w0*relu(acc0) + w1*relu(acc1)) @ Wc + bc
__global__ void __launch_bounds__(256, 2) k_final(const float* __restrict__ fw,
                                                  const float* __restrict__ Wc,
                                                  const float* __restrict__ bc,
                                                  float* __restrict__ out) {
    __shared__ float AsD[32][256];
    __shared__ float Bs [32][64];
    int tid = threadIdx.x;
    int tx  = tid & 15;              // cols tx*4 .. tx*4+3
    int ty  = tid >> 4;              // rows ty*8 .. ty*8+7
    int m0  = blockIdx.x * 128;

    float f0 = fw[0], f1 = fw[1];
    float mx = fmaxf(f0, f1);
    float e0 = __expf(f0 - mx), e1 = __expf(f1 - mx);
    float w0 = e0 / (e0 + e1), w1 = 1.0f - w0;

    unsigned long long acc[8][2];
#pragma unroll
    for (int m = 0; m < 8; m++) { acc[m][0] = 0ull; acc[m][1] = 0ull; }

    for (int k0 = 0; k0 < DIM; k0 += 32) {
#pragma unroll
        for (int l = 0; l < 4; l++) {
            int f  = tid + l * 256;
            int r  = f & 127;
            int kv = f >> 7;
            float4 h = make_float4(0.f, 0.f, 0.f, 0.f);
            int gr = m0 + r;
            if (gr < NN) {
                size_t off = (size_t)gr * DIM + k0 + kv * 4;
                float4 a0 = *(const float4*)(g_acc0 + off);
                float4 a1 = *(const float4*)(g_acc1 + off);
                h.x = w0 * fmaxf(a0.x, 0.f) + w1 * fmaxf(a1.x, 0.f);
                h.y = w0 * fmaxf(a0.y, 0.f) + w1 * fmaxf(a1.y, 0.f);
                h.z = w0 * fmaxf(a0.z, 0.f) + w1 * fmaxf(a1.z, 0.f);
                h.w = w0 * fmaxf(a0.w, 0.f) + w1 * fmaxf(a1.w, 0.f);
            }
            *(float2*)&AsD[kv * 4 + 0][2 * r] = make_float2(h.x, h.x);
            *(float2*)&AsD[kv * 4 + 1][2 * r] = make_float2(h.y, h.y);
            *(float2*)&AsD[kv * 4 + 2][2 * r] = make_float2(h.z, h.z);
            *(float2*)&AsD[kv * 4 + 3][2 * r] = make_float2(h.w, h.w);
        }
#pragma unroll
        for (int l = 0; l < 2; l++) {
            int f  = tid + l * 256;
            int k  = f >> 4;
            int cv = f & 15;
            *(float4*)&Bs[k][cv * 4] = *(const float4*)(Wc + (size_t)(k0 + k) * OUTD + cv * 4);
        }
        __syncthreads();

#pragma unroll
        for (int k = 0; k < 32; k++) {
            ulonglong2 a01 = *(const ulonglong2*)&AsD[k][ty * 16 + 0];
            ulonglong2 a23 = *(const ulonglong2*)&AsD[k][ty * 16 + 4];
            ulonglong2 a45 = *(const ulonglong2*)&AsD[k][ty * 16 + 8];
            ulonglong2 a67 = *(const ulonglong2*)&AsD[k][ty * 16 + 12];
            ulonglong2 b01 = *(const ulonglong2*)&Bs[k][tx * 4];
            unsigned long long av[8] = {a01.x, a01.y, a23.x, a23.y,
                                        a45.x, a45.y, a67.x, a67.y};
            unsigned long long bv[2] = {b01.x, b01.y};
#pragma unroll
            for (int m = 0; m < 8; m++)
#pragma unroll
                for (int p = 0; p < 2; p++)
                    asm("fma.rn.f32x2 %0, %1, %2, %0;"
                        : "+l"(acc[m][p]) : "l"(av[m]), "l"(bv[p]));
        }
        __syncthreads();
    }

    float4 bb = *(const float4*)(bc + tx * 4);
#pragma unroll
    for (int m = 0; m < 8; m++) {
        int gr = m0 + ty * 8 + m;
        if (gr >= NN) continue;
        float4 o;
        o.x = lo32(acc[m][0]) + bb.x;
        o.y = hi32(acc[m][0]) + bb.y;
        o.z = lo32(acc[m][1]) + bb.z;
        o.w = hi32(acc[m][1]) + bb.w;
        *(float4*)(out + (size_t)gr * OUTD + tx * 4) = o;
    }
}

// ---------------- host orchestration ---------------------------------------
extern "C" void kernel_launch(void* const* d_in, const int* in_sizes, int n_in,
                              void* d_out, int out_size) {
    const float* x      = (const float*)d_in[0];
    const int*   ei     = (const int*)d_in[1];
    const int*   gei    = (const int*)d_in[2];
    const float* w_orig = (const float*)d_in[3];
    const float* b_orig = (const float*)d_in[4];
    const float* w_aug  = (const float*)d_in[5];
    const float* b_aug  = (const float*)d_in[6];
    const float* fw     = (const float*)d_in[7];
    const float* clfw   = (const float*)d_in[8];
    const float* clfb   = (const float*)d_in[9];
    float*       out    = (float*)d_out;

    float *acc0, *acc1, *bufA, *bufB;
    cudaGetSymbolAddress((void**)&acc0, g_acc0);
    cudaGetSymbolAddress((void**)&acc1, g_acc1);
    cudaGetSymbolAddress((void**)&bufA, g_bufA);
    cudaGetSymbolAddress((void**)&bufB, g_bufB);

    const int TB = 256;
    dim3 gN((NN + TB - 1) / TB);
    dim3 gE((EE + TB - 1) / TB);

    for (int g = 0; g < 2; g++) {
        const int*   edges = g ? gei : ei;
        const float* W     = g ? w_aug : w_orig;
        const float* b     = g ? b_aug : b_orig;
        float*       acc   = g ? acc1  : acc0;

        // CSR build
        k_deg_init <<<gN, TB>>>();
        k_deg_count<<<gE, TB>>>(edges);
        k_deg_fin  <<<gN, TB>>>();
        k_scan1<<<NB_SCAN, 512>>>();
        k_scan2<<<1, 256>>>();
        k_scan3<<<gN, TB>>>();
        k_fill <<<gE, TB>>>(edges);

        // fused chain: gemm_i overlapped with pull_{i+1}
        // fused0: gemm(x,W0,bias) + pull(x -> bufA)
        k_fused<<<FUSE_GRID, TB>>>(x, W, acc, b, x, bufA);
        // fused1: gemm(bufA,W1) + pull(bufA -> bufB)
        k_fused<<<FUSE_GRID, TB>>>(bufA, W + 1 * DIM * DIM, acc, nullptr, bufA, bufB);
        // fused2: gemm(bufB,W2) + pull(bufB -> bufA)
        k_fused<<<FUSE_GRID, TB>>>(bufB, W + 2 * DIM * DIM, acc, nullptr, bufB, bufA);
        // fused3: gemm(bufA,W3) + pull(bufA -> bufB)
        k_fused<<<FUSE_GRID, TB>>>(bufA, W + 3 * DIM * DIM, acc, nullptr, bufA, bufB);
        // tail gemm on the 4th-hop output
        k_gemm<<<GEMM_BLKS, TB>>>(bufB, W + 4 * DIM * DIM, acc, nullptr);
    }

    k_final<<<GEMM_BLKS, TB>>>(fw, clfw, clfb, out);
}

// round 12
// speedup vs baseline: 1.3500x; 1.3500x over previous
#include <cuda_runtime.h>

#define NN   100000
#define EE   1600000
#define DIM  128
#define OUTD 64
#define NB_SCAN 196      // ceil(NN/512)
#define GEMM_BLKS 782    // ceil(NN/128)

// ---------------- scratch (device globals; no allocation allowed) ----------
__device__ float g_dinv[NN];
__device__ int   g_cnt[NN];
__device__ int   g_off[NN + 1];
__device__ int   g_cur[NN];
__device__ int   g_bsum[256];
__device__ int2  g_adj[EE];                  // (src_row, scale_as_float_bits)
__device__ float g_acc0[(size_t)NN * DIM];
__device__ float g_acc1[(size_t)NN * DIM];
__device__ float g_bufA[(size_t)NN * DIM];
__device__ float g_bufB[(size_t)NN * DIM];

__device__ __forceinline__ float lo32(unsigned long long u) {
    return __uint_as_float((unsigned)u);
}
__device__ __forceinline__ float hi32(unsigned long long u) {
    return __uint_as_float((unsigned)(u >> 32));
}

// ---------------- degree -----------------------------------------------------
__global__ void k_deg_init() {
    int i = blockIdx.x * blockDim.x + threadIdx.x;
    if (i < NN) g_cnt[i] = 0;
}
__global__ void k_deg_count(const int* __restrict__ ei) {
    int i = blockIdx.x * blockDim.x + threadIdx.x;
    if (i < EE) atomicAdd(&g_cnt[ei[EE + i]], 1);
}
__global__ void k_deg_fin() {
    int i = blockIdx.x * blockDim.x + threadIdx.x;
    if (i < NN) g_dinv[i] = rsqrtf((float)g_cnt[i] + 1.0f);   // +1 self loop
}

// ---------------- exclusive scan of g_cnt -> g_off ---------------------------
__global__ void k_scan1() {               // 512 threads per block
    __shared__ int s[512];
    int t = threadIdx.x;
    int i = blockIdx.x * 512 + t;
    int v = (i < NN) ? g_cnt[i] : 0;
    s[t] = v;
    __syncthreads();
#pragma unroll
    for (int off = 1; off < 512; off <<= 1) {
        int u = (t >= off) ? s[t - off] : 0;
        __syncthreads();
        s[t] += u;
        __syncthreads();
    }
    if (i < NN) { g_off[i] = s[t] - v; g_cur[i] = 0; }
    if (t == 511) g_bsum[blockIdx.x] = s[511];
}
__global__ void k_scan2() {               // 1 block, 256 threads
    __shared__ int s[256];
    int t = threadIdx.x;
    int v = (t < NB_SCAN) ? g_bsum[t] : 0;
    s[t] = v;
    __syncthreads();
#pragma unroll
    for (int off = 1; off < 256; off <<= 1) {
        int u = (t >= off) ? s[t - off] : 0;
        __syncthreads();
        s[t] += u;
        __syncthreads();
    }
    if (t < NB_SCAN) g_bsum[t] = s[t] - v;
}
__global__ void k_scan3() {
    int i = blockIdx.x * blockDim.x + threadIdx.x;
    if (i < NN) g_off[i] += g_bsum[i >> 9];
    if (i == 0) g_off[NN] = EE;
}

// ---------------- CSR fill ---------------------------------------------------
__global__ void k_fill(const int* __restrict__ ei) {
    int i = blockIdx.x * blockDim.x + threadIdx.x;
    if (i >= EE) return;
    int r = ei[i];
    int c = ei[EE + i];
    int pos = g_off[c] + atomicAdd(&g_cur[c], 1);
    float s = g_dinv[r] * g_dinv[c];
    g_adj[pos] = make_int2(r, __float_as_int(s));
}

// ---------------- hop: CSR pull (one warp per node, self-loop fused) ---------
__global__ void k_pull(const float* __restrict__ src, float* __restrict__ dst) {
    int w = (blockIdx.x * blockDim.x + threadIdx.x) >> 5;
    if (w >= NN) return;
    int lane = threadIdx.x & 31;
    int beg = g_off[w];
    int end = g_off[w + 1];
    float d = g_dinv[w];
    float dd = d * d;
    float4 acc = ((const float4*)(src + (size_t)w * DIM))[lane];
    acc.x *= dd; acc.y *= dd; acc.z *= dd; acc.w *= dd;
#pragma unroll 8
    for (int j = beg; j < end; j++) {
        int2 e = __ldg(&g_adj[j]);
        float s = __int_as_float(e.y);
        float4 v = ((const float4*)(src + (size_t)e.x * DIM))[lane];
        acc.x += s * v.x; acc.y += s * v.y;
        acc.z += s * v.z; acc.w += s * v.w;
    }
    ((float4*)(dst + (size_t)w * DIM))[lane] = acc;
}

// ---------------- GEMM (FFMA2): C[128-tile][128] (+)= A[*][128]*B[128][128] --
// BM=128, BN=128, BK=32, 256 threads, TM=8, TN=8 (4 packed f32x2 pairs)
// Register-prefetch pipeline: next k0 tile is loaded into registers before the
// FFMA2 block of the current k0, hiding L2 latency behind compute.
__global__ void __launch_bounds__(256, 2) k_gemm_acc(const float* __restrict__ A,
                                                     const float* __restrict__ B,
                                                     float* __restrict__ C,
                                                     const float* __restrict__ bias) {
    __shared__ float AsD[32][256];   // 32 KB, A[m][k] duplicated pairs
    __shared__ float Bs [32][128];   // 16 KB
    int tid = threadIdx.x;
    int tx  = tid & 15;              // cols tx*8 .. tx*8+7
    int ty  = tid >> 4;              // rows ty*8 .. ty*8+7
    int m0  = blockIdx.x * 128;

    // per-thread load coordinates (fixed across k0 iterations)
    int ra[4], kva[4], gra[4];
    int kb[4], cvb[4];
#pragma unroll
    for (int l = 0; l < 4; l++) {
        int f  = tid + l * 256;
        ra[l]  = f & 127;
        kva[l] = f >> 7;
        gra[l] = m0 + ra[l];
        kb[l]  = f >> 5;
        cvb[l] = f & 31;
    }

    unsigned long long acc[8][4];
#pragma unroll
    for (int m = 0; m < 8; m++)
#pragma unroll
        for (int p = 0; p < 4; p++) acc[m][p] = 0ull;

    // prologue: load k0=0 tile into registers
    float4 va[4], vb[4];
#pragma unroll
    for (int l = 0; l < 4; l++) {
        va[l] = make_float4(0.f, 0.f, 0.f, 0.f);
        if (gra[l] < NN) va[l] = *(const float4*)(A + (size_t)gra[l] * DIM + kva[l] * 4);
        vb[l] = *(const float4*)(B + (size_t)kb[l] * DIM + cvb[l] * 4);
    }

    for (int k0 = 0; k0 < DIM; k0 += 32) {
        // store current tile to smem
#pragma unroll
        for (int l = 0; l < 4; l++) {
            *(float2*)&AsD[kva[l] * 4 + 0][2 * ra[l]] = make_float2(va[l].x, va[l].x);
            *(float2*)&AsD[kva[l] * 4 + 1][2 * ra[l]] = make_float2(va[l].y, va[l].y);
            *(float2*)&AsD[kva[l] * 4 + 2][2 * ra[l]] = make_float2(va[l].z, va[l].z);
            *(float2*)&AsD[kva[l] * 4 + 3][2 * ra[l]] = make_float2(va[l].w, va[l].w);
            *(float4*)&Bs[kb[l]][cvb[l] * 4] = vb[l];
        }
        __syncthreads();

        // prefetch next tile into registers (overlaps with FFMA2 below)
        int kn = k0 + 32;
        if (kn < DIM) {
#pragma unroll
            for (int l = 0; l < 4; l++) {
                va[l] = make_float4(0.f, 0.f, 0.f, 0.f);
                if (gra[l] < NN)
                    va[l] = *(const float4*)(A + (size_t)gra[l] * DIM + kn + kva[l] * 4);
                vb[l] = *(const float4*)(B + (size_t)(kn + kb[l]) * DIM + cvb[l] * 4);
            }
        }

#pragma unroll
        for (int k = 0; k < 32; k++) {
            ulonglong2 a01 = *(const ulonglong2*)&AsD[k][ty * 16 + 0];
            ulonglong2 a23 = *(const ulonglong2*)&AsD[k][ty * 16 + 4];
            ulonglong2 a45 = *(const ulonglong2*)&AsD[k][ty * 16 + 8];
            ulonglong2 a67 = *(const ulonglong2*)&AsD[k][ty * 16 + 12];
            ulonglong2 b01 = *(const ulonglong2*)&Bs[k][tx * 8 + 0];
            ulonglong2 b23 = *(const ulonglong2*)&Bs[k][tx * 8 + 4];
            unsigned long long av[8] = {a01.x, a01.y, a23.x, a23.y,
                                        a45.x, a45.y, a67.x, a67.y};
            unsigned long long bv[4] = {b01.x, b01.y, b23.x, b23.y};
#pragma unroll
            for (int m = 0; m < 8; m++)
#pragma unroll
                for (int p = 0; p < 4; p++)
                    asm("fma.rn.f32x2 %0, %1, %2, %0;"
                        : "+l"(acc[m][p]) : "l"(av[m]), "l"(bv[p]));
        }
        __syncthreads();
    }

    float bsum[8];
    if (bias) {
#pragma unroll
        for (int j = 0; j < 8; j++) {
            int c = tx * 8 + j;
            bsum[j] = bias[c] + bias[DIM + c] + bias[2 * DIM + c]
                    + bias[3 * DIM + c] + bias[4 * DIM + c];
        }
    }
#pragma unroll
    for (int m = 0; m < 8; m++) {
        int gr = m0 + ty * 8 + m;
        if (gr >= NN) continue;
        float* row = C + (size_t)gr * DIM + tx * 8;
        float r0 = lo32(acc[m][0]), r1 = hi32(acc[m][0]);
        float r2 = lo32(acc[m][1]), r3 = hi32(acc[m][1]);
        float r4 = lo32(acc[m][2]), r5 = hi32(acc[m][2]);
        float r6 = lo32(acc[m][3]), r7 = hi32(acc[m][3]);
        if (bias) {
            r0 += bsum[0]; r1 += bsum[1]; r2 += bsum[2]; r3 += bsum[3];
            r4 += bsum[4]; r5 += bsum[5]; r6 += bsum[6]; r7 += bsum[7];
        } else {
            float4 c0 = *(float4*)(row);
            float4 c1 = *(float4*)(row + 4);
            r0 += c0.x; r1 += c0.y; r2 += c0.z; r3 += c0.w;
            r4 += c1.x; r5 += c1.y; r6 += c1.z; r7 += c1.w;
        }
        *(float4*)(row)     = make_float4(r0, r1, r2, r3);
        *(float4*)(row + 4) = make_float4(r4, r5, r6, r7);
    }
}

// ---------------- fusion + classifier (FFMA2) --------------------------------
// out = (w0*relu(acc0) + w1*relu(acc1)) @ Wc + bc
__global__ void __launch_bounds__(256, 2) k_final(const float* __restrict__ fw,
                                                  const float* __restrict__ Wc,
                                                  const float* __restrict__ bc,
                                                  float* __restrict__ out) {
    __shared__ float AsD[32][256];
    __shared__ float Bs [32][64];
    int tid = threadIdx.x;
    int tx  = tid & 15;              // cols tx*4 .. tx*4+3
    int ty  = tid >> 4;              // rows ty*8 .. ty*8+7
    int m0  = blockIdx.x * 128;

    float f0 = fw[0], f1 = fw[1];
    float mx = fmaxf(f0, f1);
    float e0 = __expf(f0 - mx), e1 = __expf(f1 - mx);
    float w0 = e0 / (e0 + e1), w1 = 1.0f - w0;

    unsigned long long acc[8][2];
#pragma unroll
    for (int m = 0; m < 8; m++) { acc[m][0] = 0ull; acc[m][1] = 0ull; }

    for (int k0 = 0; k0 < DIM; k0 += 32) {
#pragma unroll
        for (int l = 0; l < 4; l++) {
            int f  = tid + l * 256;
            int r  = f & 127;
            int kv = f >> 7;
            float4 h = make_float4(0.f, 0.f, 0.f, 0.f);
            int gr = m0 + r;
            if (gr < NN) {
                size_t off = (size_t)gr * DIM + k0 + kv * 4;
                float4 a0 = *(const float4*)(g_acc0 + off);
                float4 a1 = *(const float4*)(g_acc1 + off);
                h.x = w0 * fmaxf(a0.x, 0.f) + w1 * fmaxf(a1.x, 0.f);
                h.y = w0 * fmaxf(a0.y, 0.f) + w1 * fmaxf(a1.y, 0.f);
                h.z = w0 * fmaxf(a0.z, 0.f) + w1 * fmaxf(a1.z, 0.f);
                h.w = w0 * fmaxf(a0.w, 0.f) + w1 * fmaxf(a1.w, 0.f);
            }
            *(float2*)&AsD[kv * 4 + 0][2 * r] = make_float2(h.x, h.x);
            *(float2*)&AsD[kv * 4 + 1][2 * r] = make_float2(h.y, h.y);
            *(float2*)&AsD[kv * 4 + 2][2 * r] = make_float2(h.z, h.z);
            *(float2*)&AsD[kv * 4 + 3][2 * r] = make_float2(h.w, h.w);
        }
#pragma unroll
        for (int l = 0; l < 2; l++) {
            int f  = tid + l * 256;
            int k  = f >> 4;
            int cv = f & 15;
            *(float4*)&Bs[k][cv * 4] = *(const float4*)(Wc + (size_t)(k0 + k) * OUTD + cv * 4);
        }
        __syncthreads();

#pragma unroll
        for (int k = 0; k < 32; k++) {
            ulonglong2 a01 = *(const ulonglong2*)&AsD[k][ty * 16 + 0];
            ulonglong2 a23 = *(const ulonglong2*)&AsD[k][ty * 16 + 4];
            ulonglong2 a45 = *(const ulonglong2*)&AsD[k][ty * 16 + 8];
            ulonglong2 a67 = *(const ulonglong2*)&AsD[k][ty * 16 + 12];
            ulonglong2 b01 = *(const ulonglong2*)&Bs[k][tx * 4];
            unsigned long long av[8] = {a01.x, a01.y, a23.x, a23.y,
                                        a45.x, a45.y, a67.x, a67.y};
            unsigned long long bv[2] = {b01.x, b01.y};
#pragma unroll
            for (int m = 0; m < 8; m++)
#pragma unroll
                for (int p = 0; p < 2; p++)
                    asm("fma.rn.f32x2 %0, %1, %2, %0;"
                        : "+l"(acc[m][p]) : "l"(av[m]), "l"(bv[p]));
        }
        __syncthreads();
    }

    float4 bb = *(const float4*)(bc + tx * 4);
#pragma unroll
    for (int m = 0; m < 8; m++) {
        int gr = m0 + ty * 8 + m;
        if (gr >= NN) continue;
        float4 o;
        o.x = lo32(acc[m][0]) + bb.x;
        o.y = hi32(acc[m][0]) + bb.y;
        o.z = lo32(acc[m][1]) + bb.z;
        o.w = hi32(acc[m][1]) + bb.w;
        *(float4*)(out + (size_t)gr * OUTD + tx * 4) = o;
    }
}

// ---------------- host orchestration ---------------------------------------
extern "C" void kernel_launch(void* const* d_in, const int* in_sizes, int n_in,
                              void* d_out, int out_size) {
    const float* x      = (const float*)d_in[0];
    const int*   ei     = (const int*)d_in[1];
    const int*   gei    = (const int*)d_in[2];
    const float* w_orig = (const float*)d_in[3];
    const float* b_orig = (const float*)d_in[4];
    const float* w_aug  = (const float*)d_in[5];
    const float* b_aug  = (const float*)d_in[6];
    const float* fw     = (const float*)d_in[7];
    const float* clfw   = (const float*)d_in[8];
    const float* clfb   = (const float*)d_in[9];
    float*       out    = (float*)d_out;

    float *acc0, *acc1, *bufA, *bufB;
    cudaGetSymbolAddress((void**)&acc0, g_acc0);
    cudaGetSymbolAddress((void**)&acc1, g_acc1);
    cudaGetSymbolAddress((void**)&bufA, g_bufA);
    cudaGetSymbolAddress((void**)&bufB, g_bufB);

    const int TB = 256;
    dim3 gN((NN + TB - 1) / TB);
    dim3 gE((EE + TB - 1) / TB);
    dim3 gP((NN * 32 + TB - 1) / TB);        // pull: 1 warp/node

    for (int g = 0; g < 2; g++) {
        const int*   edges = g ? gei : ei;
        const float* W     = g ? w_aug : w_orig;
        const float* b     = g ? b_aug : b_orig;
        float*       acc   = g ? acc1  : acc0;

        // CSR build
        k_deg_init <<<gN, TB>>>();
        k_deg_count<<<gE, TB>>>(edges);
        k_deg_fin  <<<gN, TB>>>();
        k_scan1<<<NB_SCAN, 512>>>();
        k_scan2<<<1, 256>>>();
        k_scan3<<<gN, TB>>>();
        k_fill <<<gE, TB>>>(edges);

        k_gemm_acc<<<GEMM_BLKS, TB>>>(x, W, acc, b);   // order-0 term, bias-init

        const float* src = x;
        float*       dst = bufA;
        for (int i = 1; i <= 4; i++) {
            k_pull<<<gP, TB>>>(src, dst);
            k_gemm_acc<<<GEMM_BLKS, TB>>>(dst, W + (size_t)i * DIM * DIM, acc, nullptr);
            src = dst;
            dst = (dst == bufA) ? bufB : bufA;
        }
    }

    k_final<<<GEMM_BLKS, TB>>>(fw, clfw, clfb, out);
}

// round 13
// speedup vs baseline: 1.4724x; 1.0906x over previous
#include <cuda_runtime.h>

#define NN   100000
#define EE   1600000
#define DIM  128
#define OUTD 64
#define NB_SCAN 196      // ceil(NN/512)
#define GEMM_BLKS 782    // ceil(NN/128)

// ---------------- scratch (device globals; no allocation allowed) ----------
__device__ float g_dinv[NN];
__device__ int   g_cnt[NN];
__device__ int   g_off[NN + 1];
__device__ int   g_cur[NN];
__device__ int   g_bsum[256];
__device__ int2  g_adj[EE];                  // (src_row, scale_as_float_bits)
__device__ float g_acc0[(size_t)NN * DIM];
__device__ float g_acc1[(size_t)NN * DIM];
__device__ float g_bufA[(size_t)NN * DIM];
__device__ float g_bufB[(size_t)NN * DIM];

__device__ __forceinline__ float lo32(unsigned long long u) {
    return __uint_as_float((unsigned)u);
}
__device__ __forceinline__ float hi32(unsigned long long u) {
    return __uint_as_float((unsigned)(u >> 32));
}

// ---------------- degree -----------------------------------------------------
__global__ void k_deg_init() {
    int i = blockIdx.x * blockDim.x + threadIdx.x;
    if (i < NN) g_cnt[i] = 0;
}
__global__ void k_deg_count(const int* __restrict__ ei) {
    int i = blockIdx.x * blockDim.x + threadIdx.x;
    if (i < EE) atomicAdd(&g_cnt[ei[EE + i]], 1);
}

// ---------------- scan1 (+ deg_fin fused) ------------------------------------
__global__ void k_scan1() {               // 512 threads per block
    __shared__ int s[512];
    int t = threadIdx.x;
    int i = blockIdx.x * 512 + t;
    int v = (i < NN) ? g_cnt[i] : 0;
    s[t] = v;
    __syncthreads();
#pragma unroll
    for (int off = 1; off < 512; off <<= 1) {
        int u = (t >= off) ? s[t - off] : 0;
        __syncthreads();
        s[t] += u;
        __syncthreads();
    }
    if (i < NN) {
        g_off[i] = s[t] - v;
        g_cur[i] = 0;
        g_dinv[i] = rsqrtf((float)v + 1.0f);   // +1 self loop (fused deg_fin)
    }
    if (t == 511) g_bsum[blockIdx.x] = s[511];
}
__global__ void k_scan2() {               // 1 block, 256 threads
    __shared__ int s[256];
    int t = threadIdx.x;
    int v = (t < NB_SCAN) ? g_bsum[t] : 0;
    s[t] = v;
    __syncthreads();
#pragma unroll
    for (int off = 1; off < 256; off <<= 1) {
        int u = (t >= off) ? s[t - off] : 0;
        __syncthreads();
        s[t] += u;
        __syncthreads();
    }
    if (t < NB_SCAN) g_bsum[t] = s[t] - v;
}
__global__ void k_scan3() {
    int i = blockIdx.x * blockDim.x + threadIdx.x;
    if (i < NN) g_off[i] += g_bsum[i >> 9];
    if (i == 0) g_off[NN] = EE;
}

// ---------------- CSR fill ---------------------------------------------------
__global__ void k_fill(const int* __restrict__ ei) {
    int i = blockIdx.x * blockDim.x + threadIdx.x;
    if (i >= EE) return;
    int r = ei[i];
    int c = ei[EE + i];
    int pos = g_off[c] + atomicAdd(&g_cur[c], 1);
    float s = g_dinv[r] * g_dinv[c];
    g_adj[pos] = make_int2(r, __float_as_int(s));
}

// ---------------- hop: CSR pull (one warp per node, self-loop fused) ---------
__global__ void k_pull(const float* __restrict__ src, float* __restrict__ dst) {
    int w = (blockIdx.x * blockDim.x + threadIdx.x) >> 5;
    if (w >= NN) return;
    int lane = threadIdx.x & 31;
    int beg = g_off[w];
    int end = g_off[w + 1];
    float d = g_dinv[w];
    float dd = d * d;
    float4 acc = ((const float4*)(src + (size_t)w * DIM))[lane];
    acc.x *= dd; acc.y *= dd; acc.z *= dd; acc.w *= dd;
#pragma unroll 4
    for (int j = beg; j < end; j++) {
        int2 e = __ldg(&g_adj[j]);
        float s = __int_as_float(e.y);
        float4 v = ((const float4*)(src + (size_t)e.x * DIM))[lane];
        acc.x += s * v.x; acc.y += s * v.y;
        acc.z += s * v.z; acc.w += s * v.w;
    }
    ((float4*)(dst + (size_t)w * DIM))[lane] = acc;
}

// ---------------- GEMM (FFMA2): C[128-tile][128] (+)= A[*][128]*B[128][128] --
// BM=128, BN=128, BK=32, 256 threads, TM=8, TN=8 (4 packed f32x2 pairs)
__global__ void __launch_bounds__(256, 2) k_gemm_acc(const float* __restrict__ A,
                                                     const float* __restrict__ B,
                                                     float* __restrict__ C,
                                                     const float* __restrict__ bias) {
    __shared__ float AsD[32][256];   // 32 KB, A[m][k] duplicated pairs
    __shared__ float Bs [32][128];   // 16 KB
    int tid = threadIdx.x;
    int tx  = tid & 15;              // cols tx*8 .. tx*8+7
    int ty  = tid >> 4;              // rows ty*8 .. ty*8+7
    int m0  = blockIdx.x * 128;

    unsigned long long acc[8][4];
#pragma unroll
    for (int m = 0; m < 8; m++)
#pragma unroll
        for (int p = 0; p < 4; p++) acc[m][p] = 0ull;

    for (int k0 = 0; k0 < DIM; k0 += 32) {
#pragma unroll
        for (int l = 0; l < 4; l++) {
            int f  = tid + l * 256;
            int r  = f & 127;
            int kv = f >> 7;
            float4 v = make_float4(0.f, 0.f, 0.f, 0.f);
            int gr = m0 + r;
            if (gr < NN) v = *(const float4*)(A + (size_t)gr * DIM + k0 + kv * 4);
            *(float2*)&AsD[kv * 4 + 0][2 * r] = make_float2(v.x, v.x);
            *(float2*)&AsD[kv * 4 + 1][2 * r] = make_float2(v.y, v.y);
            *(float2*)&AsD[kv * 4 + 2][2 * r] = make_float2(v.z, v.z);
            *(float2*)&AsD[kv * 4 + 3][2 * r] = make_float2(v.w, v.w);
        }
#pragma unroll
        for (int l = 0; l < 4; l++) {
            int f  = tid + l * 256;
            int k  = f >> 5;
            int cv = f & 31;
            *(float4*)&Bs[k][cv * 4] = *(const float4*)(B + (size_t)(k0 + k) * DIM + cv * 4);
        }
        __syncthreads();

#pragma unroll
        for (int k = 0; k < 32; k++) {
            ulonglong2 a01 = *(const ulonglong2*)&AsD[k][ty * 16 + 0];
            ulonglong2 a23 = *(const ulonglong2*)&AsD[k][ty * 16 + 4];
            ulonglong2 a45 = *(const ulonglong2*)&AsD[k][ty * 16 + 8];
            ulonglong2 a67 = *(const ulonglong2*)&AsD[k][ty * 16 + 12];
            ulonglong2 b01 = *(const ulonglong2*)&Bs[k][tx * 8 + 0];
            ulonglong2 b23 = *(const ulonglong2*)&Bs[k][tx * 8 + 4];
            unsigned long long av[8] = {a01.x, a01.y, a23.x, a23.y,
                                        a45.x, a45.y, a67.x, a67.y};
            unsigned long long bv[4] = {b01.x, b01.y, b23.x, b23.y};
#pragma unroll
            for (int m = 0; m < 8; m++)
#pragma unroll
                for (int p = 0; p < 4; p++)
                    asm("fma.rn.f32x2 %0, %1, %2, %0;"
                        : "+l"(acc[m][p]) : "l"(av[m]), "l"(bv[p]));
        }
        __syncthreads();
    }

    float bsum[8];
    if (bias) {
#pragma unroll
        for (int j = 0; j < 8; j++) {
            int c = tx * 8 + j;
            bsum[j] = bias[c] + bias[DIM + c] + bias[2 * DIM + c]
                    + bias[3 * DIM + c] + bias[4 * DIM + c];
        }
    }
#pragma unroll
    for (int m = 0; m < 8; m++) {
        int gr = m0 + ty * 8 + m;
        if (gr >= NN) continue;
        float* row = C + (size_t)gr * DIM + tx * 8;
        float r0 = lo32(acc[m][0]), r1 = hi32(acc[m][0]);
        float r2 = lo32(acc[m][1]), r3 = hi32(acc[m][1]);
        float r4 = lo32(acc[m][2]), r5 = hi32(acc[m][2]);
        float r6 = lo32(acc[m][3]), r7 = hi32(acc[m][3]);
        if (bias) {
            r0 += bsum[0]; r1 += bsum[1]; r2 += bsum[2]; r3 += bsum[3];
            r4 += bsum[4]; r5 += bsum[5]; r6 += bsum[6]; r7 += bsum[7];
        } else {
            float4 c0 = *(float4*)(row);
            float4 c1 = *(float4*)(row + 4);
            r0 += c0.x; r1 += c0.y; r2 += c0.z; r3 += c0.w;
            r4 += c1.x; r5 += c1.y; r6 += c1.z; r7 += c1.w;
        }
        *(float4*)(row)     = make_float4(r0, r1, r2, r3);
        *(float4*)(row + 4) = make_float4(r4, r5, r6, r7);
    }
}

// ---------------- fusion + classifier (FFMA2) --------------------------------
// out = (w0*relu(acc0) + w1*relu(acc1)) @ Wc + bc
__global__ void __launch_bounds__(256, 2) k_final(const float* __restrict__ fw,
                                                  const float* __restrict__ Wc,
                                                  const float* __restrict__ bc,
                                                  float* __restrict__ out) {
    __shared__ float AsD[32][256];
    __shared__ float Bs [32][64];
    int tid = threadIdx.x;
    int tx  = tid & 15;              // cols tx*4 .. tx*4+3
    int ty  = tid >> 4;              // rows ty*8 .. ty*8+7
    int m0  = blockIdx.x * 128;

    float f0 = fw[0], f1 = fw[1];
    float mx = fmaxf(f0, f1);
    float e0 = __expf(f0 - mx), e1 = __expf(f1 - mx);
    float w0 = e0 / (e0 + e1), w1 = 1.0f - w0;

    unsigned long long acc[8][2];
#pragma unroll
    for (int m = 0; m < 8; m++) { acc[m][0] = 0ull; acc[m][1] = 0ull; }

    for (int k0 = 0; k0 < DIM; k0 += 32) {
#pragma unroll
        for (int l = 0; l < 4; l++) {
            int f  = tid + l * 256;
            int r  = f & 127;
            int kv = f >> 7;
            float4 h = make_float4(0.f, 0.f, 0.f, 0.f);
            int gr = m0 + r;
            if (gr < NN) {
                size_t off = (size_t)gr * DIM + k0 + kv * 4;
                float4 a0 = *(const float4*)(g_acc0 + off);
                float4 a1 = *(const float4*)(g_acc1 + off);
                h.x = w0 * fmaxf(a0.x, 0.f) + w1 * fmaxf(a1.x, 0.f);
                h.y = w0 * fmaxf(a0.y, 0.f) + w1 * fmaxf(a1.y, 0.f);
                h.z = w0 * fmaxf(a0.z, 0.f) + w1 * fmaxf(a1.z, 0.f);
                h.w = w0 * fmaxf(a0.w, 0.f) + w1 * fmaxf(a1.w, 0.f);
            }
            *(float2*)&AsD[kv * 4 + 0][2 * r] = make_float2(h.x, h.x);
            *(float2*)&AsD[kv * 4 + 1][2 * r] = make_float2(h.y, h.y);
            *(float2*)&AsD[kv * 4 + 2][2 * r] = make_float2(h.z, h.z);
            *(float2*)&AsD[kv * 4 + 3][2 * r] = make_float2(h.w, h.w);
        }
#pragma unroll
        for (int l = 0; l < 2; l++) {
            int f  = tid + l * 256;
            int k  = f >> 4;
            int cv = f & 15;
            *(float4*)&Bs[k][cv * 4] = *(const float4*)(Wc + (size_t)(k0 + k) * OUTD + cv * 4);
        }
        __syncthreads();

#pragma unroll
        for (int k = 0; k < 32; k++) {
            ulonglong2 a01 = *(const ulonglong2*)&AsD[k][ty * 16 + 0];
            ulonglong2 a23 = *(const ulonglong2*)&AsD[k][ty * 16 + 4];
            ulonglong2 a45 = *(const ulonglong2*)&AsD[k][ty * 16 + 8];
            ulonglong2 a67 = *(const ulonglong2*)&AsD[k][ty * 16 + 12];
            ulonglong2 b01 = *(const ulonglong2*)&Bs[k][tx * 4];
            unsigned long long av[8] = {a01.x, a01.y, a23.x, a23.y,
                                        a45.x, a45.y, a67.x, a67.y};
            unsigned long long bv[2] = {b01.x, b01.y};
#pragma unroll
            for (int m = 0; m < 8; m++)
#pragma unroll
                for (int p = 0; p < 2; p++)
                    asm("fma.rn.f32x2 %0, %1, %2, %0;"
                        : "+l"(acc[m][p]) : "l"(av[m]), "l"(bv[p]));
        }
        __syncthreads();
    }

    float4 bb = *(const float4*)(bc + tx * 4);
#pragma unroll
    for (int m = 0; m < 8; m++) {
        int gr = m0 + ty * 8 + m;
        if (gr >= NN) continue;
        float4 o;
        o.x = lo32(acc[m][0]) + bb.x;
        o.y = hi32(acc[m][0]) + bb.y;
        o.z = lo32(acc[m][1]) + bb.z;
        o.w = hi32(acc[m][1]) + bb.w;
        *(float4*)(out + (size_t)gr * OUTD + tx * 4) = o;
    }
}

// ---------------- host orchestration ---------------------------------------
extern "C" void kernel_launch(void* const* d_in, const int* in_sizes, int n_in,
                              void* d_out, int out_size) {
    const float* x      = (const float*)d_in[0];
    const int*   ei     = (const int*)d_in[1];
    const int*   gei    = (const int*)d_in[2];
    const float* w_orig = (const float*)d_in[3];
    const float* b_orig = (const float*)d_in[4];
    const float* w_aug  = (const float*)d_in[5];
    const float* b_aug  = (const float*)d_in[6];
    const float* fw     = (const float*)d_in[7];
    const float* clfw   = (const float*)d_in[8];
    const float* clfb   = (const float*)d_in[9];
    float*       out    = (float*)d_out;

    float *acc0, *acc1, *bufA, *bufB;
    cudaGetSymbolAddress((void**)&acc0, g_acc0);
    cudaGetSymbolAddress((void**)&acc1, g_acc1);
    cudaGetSymbolAddress((void**)&bufA, g_bufA);
    cudaGetSymbolAddress((void**)&bufB, g_bufB);

    const int TB = 256;
    dim3 gN((NN + TB - 1) / TB);
    dim3 gE((EE + TB - 1) / TB);
    dim3 gP((NN * 32 + TB - 1) / TB);        // pull: 1 warp/node

    for (int g = 0; g < 2; g++) {
        const int*   edges = g ? gei : ei;
        const float* W     = g ? w_aug : w_orig;
        const float* b     = g ? b_aug : b_orig;
        float*       acc   = g ? acc1  : acc0;

        // CSR build (deg_fin fused into scan1). Order-0 GEMM is launch #5 on
        // branch 0 so the ncu -s 5 -c 1 window profiles the GEMM, not a scan.
        k_deg_init <<<gN, TB>>>();               // 0
        k_deg_count<<<gE, TB>>>(edges);          // 1
        k_scan1<<<NB_SCAN, 512>>>();             // 2 (+dinv)
        k_scan2<<<1, 256>>>();                   // 3
        k_scan3<<<gN, TB>>>();                   // 4
        k_gemm_acc<<<GEMM_BLKS, TB>>>(x, W, acc, b);   // 5  <- profiled
        k_fill <<<gE, TB>>>(edges);              // 6

        const float* src = x;
        float*       dst = bufA;
        for (int i = 1; i <= 4; i++) {
            k_pull<<<gP, TB>>>(src, dst);
            k_gemm_acc<<<GEMM_BLKS, TB>>>(dst, W + (size_t)i * DIM * DIM, acc, nullptr);
            src = dst;
            dst = (dst == bufA) ? bufB : bufA;
        }
    }

    k_final<<<GEMM_BLKS, TB>>>(fw, clfw, clfb, out);
}

// round 14
// speedup vs baseline: 1.6006x; 1.0871x over previous
#include <cuda_runtime.h>

#define NN   100000
#define EE   1600000
#define DIM  128
#define OUTD 64
#define NB_SCAN 196      // ceil(NN/512)
#define GEMM_BLKS 782    // ceil(NN/128)

// ---------------- scratch (device globals; no allocation allowed) ----------
__device__ float g_dinv[NN];
__device__ int   g_cnt[NN];
__device__ int   g_off[NN + 1];
__device__ int   g_cur[NN];
__device__ int   g_bsum[256];
__device__ int2  g_adj[EE];                  // (src_row, scale_as_float_bits)
__device__ float g_acc0[(size_t)NN * DIM];
__device__ float g_acc1[(size_t)NN * DIM];
__device__ float g_bufA[(size_t)NN * DIM];
__device__ float g_bufB[(size_t)NN * DIM];
__device__ float g_bufC[(size_t)NN * DIM];
__device__ float g_bufD[(size_t)NN * DIM];

__device__ __forceinline__ float lo32(unsigned long long u) {
    return __uint_as_float((unsigned)u);
}
__device__ __forceinline__ float hi32(unsigned long long u) {
    return __uint_as_float((unsigned)(u >> 32));
}

// ---------------- degree -----------------------------------------------------
__global__ void k_deg_init() {
    int i = blockIdx.x * blockDim.x + threadIdx.x;
    if (i < NN) g_cnt[i] = 0;
}
__global__ void k_deg_count(const int* __restrict__ ei) {
    int i = blockIdx.x * blockDim.x + threadIdx.x;
    if (i < EE) atomicAdd(&g_cnt[ei[EE + i]], 1);
}

// ---------------- scan1 (+ deg_fin fused) ------------------------------------
__global__ void k_scan1() {               // 512 threads per block
    __shared__ int s[512];
    int t = threadIdx.x;
    int i = blockIdx.x * 512 + t;
    int v = (i < NN) ? g_cnt[i] : 0;
    s[t] = v;
    __syncthreads();
#pragma unroll
    for (int off = 1; off < 512; off <<= 1) {
        int u = (t >= off) ? s[t - off] : 0;
        __syncthreads();
        s[t] += u;
        __syncthreads();
    }
    if (i < NN) {
        g_off[i] = s[t] - v;
        g_cur[i] = 0;
        g_dinv[i] = rsqrtf((float)v + 1.0f);   // +1 self loop (fused deg_fin)
    }
    if (t == 511) g_bsum[blockIdx.x] = s[511];
}
__global__ void k_scan2() {               // 1 block, 256 threads
    __shared__ int s[256];
    int t = threadIdx.x;
    int v = (t < NB_SCAN) ? g_bsum[t] : 0;
    s[t] = v;
    __syncthreads();
#pragma unroll
    for (int off = 1; off < 256; off <<= 1) {
        int u = (t >= off) ? s[t - off] : 0;
        __syncthreads();
        s[t] += u;
        __syncthreads();
    }
    if (t < NB_SCAN) g_bsum[t] = s[t] - v;
}
__global__ void k_scan3() {
    int i = blockIdx.x * blockDim.x + threadIdx.x;
    if (i < NN) g_off[i] += g_bsum[i >> 9];
    if (i == 0) g_off[NN] = EE;
}

// ---------------- CSR fill ---------------------------------------------------
__global__ void k_fill(const int* __restrict__ ei) {
    int i = blockIdx.x * blockDim.x + threadIdx.x;
    if (i >= EE) return;
    int r = ei[i];
    int c = ei[EE + i];
    int pos = g_off[c] + atomicAdd(&g_cur[c], 1);
    float s = g_dinv[r] * g_dinv[c];
    g_adj[pos] = make_int2(r, __float_as_int(s));
}

// ---------------- hop: CSR pull (one warp per node, self-loop fused) ---------
__global__ void k_pull(const float* __restrict__ src, float* __restrict__ dst) {
    int w = (blockIdx.x * blockDim.x + threadIdx.x) >> 5;
    if (w >= NN) return;
    int lane = threadIdx.x & 31;
    int beg = g_off[w];
    int end = g_off[w + 1];
    float d = g_dinv[w];
    float dd = d * d;
    float4 acc = ((const float4*)(src + (size_t)w * DIM))[lane];
    acc.x *= dd; acc.y *= dd; acc.z *= dd; acc.w *= dd;
#pragma unroll 4
    for (int j = beg; j < end; j++) {
        int2 e = __ldg(&g_adj[j]);
        float s = __int_as_float(e.y);
        float4 v = ((const float4*)(src + (size_t)e.x * DIM))[lane];
        acc.x += s * v.x; acc.y += s * v.y;
        acc.z += s * v.z; acc.w += s * v.w;
    }
    ((float4*)(dst + (size_t)w * DIM))[lane] = acc;
}

// ---------------- fused 5-source GEMM (FFMA2) --------------------------------
// C[128-tile][128] = sum_s A_s[*][128] * W_s[128][128]  + sum_s bias_s
// BM=128, BN=128, BK=32, 256 threads, TM=8, TN=8 (4 packed f32x2 pairs).
// Accumulator lives in registers across all 5 sources: C written exactly once.
__global__ void __launch_bounds__(256, 2) k_gemm5(const float* __restrict__ A0,
                                                  const float* __restrict__ A1,
                                                  const float* __restrict__ A2,
                                                  const float* __restrict__ A3,
                                                  const float* __restrict__ A4,
                                                  const float* __restrict__ W,
                                                  float* __restrict__ C,
                                                  const float* __restrict__ bias) {
    __shared__ float AsD[32][256];   // 32 KB, A[m][k] duplicated pairs
    __shared__ float Bs [32][128];   // 16 KB
    int tid = threadIdx.x;
    int tx  = tid & 15;              // cols tx*8 .. tx*8+7
    int ty  = tid >> 4;              // rows ty*8 .. ty*8+7
    int m0  = blockIdx.x * 128;

    unsigned long long acc[8][4];
#pragma unroll
    for (int m = 0; m < 8; m++)
#pragma unroll
        for (int p = 0; p < 4; p++) acc[m][p] = 0ull;

    for (int s = 0; s < 5; s++) {
        const float* A = (s == 0) ? A0 : (s == 1) ? A1 : (s == 2) ? A2
                       : (s == 3) ? A3 : A4;
        const float* B = W + (size_t)s * DIM * DIM;

        for (int k0 = 0; k0 < DIM; k0 += 32) {
#pragma unroll
            for (int l = 0; l < 4; l++) {
                int f  = tid + l * 256;
                int r  = f & 127;
                int kv = f >> 7;
                float4 v = make_float4(0.f, 0.f, 0.f, 0.f);
                int gr = m0 + r;
                if (gr < NN) v = *(const float4*)(A + (size_t)gr * DIM + k0 + kv * 4);
                *(float2*)&AsD[kv * 4 + 0][2 * r] = make_float2(v.x, v.x);
                *(float2*)&AsD[kv * 4 + 1][2 * r] = make_float2(v.y, v.y);
                *(float2*)&AsD[kv * 4 + 2][2 * r] = make_float2(v.z, v.z);
                *(float2*)&AsD[kv * 4 + 3][2 * r] = make_float2(v.w, v.w);
            }
#pragma unroll
            for (int l = 0; l < 4; l++) {
                int f  = tid + l * 256;
                int k  = f >> 5;
                int cv = f & 31;
                *(float4*)&Bs[k][cv * 4] = *(const float4*)(B + (size_t)(k0 + k) * DIM + cv * 4);
            }
            __syncthreads();

#pragma unroll
            for (int k = 0; k < 32; k++) {
                ulonglong2 a01 = *(const ulonglong2*)&AsD[k][ty * 16 + 0];
                ulonglong2 a23 = *(const ulonglong2*)&AsD[k][ty * 16 + 4];
                ulonglong2 a45 = *(const ulonglong2*)&AsD[k][ty * 16 + 8];
                ulonglong2 a67 = *(const ulonglong2*)&AsD[k][ty * 16 + 12];
                ulonglong2 b01 = *(const ulonglong2*)&Bs[k][tx * 8 + 0];
                ulonglong2 b23 = *(const ulonglong2*)&Bs[k][tx * 8 + 4];
                unsigned long long av[8] = {a01.x, a01.y, a23.x, a23.y,
                                            a45.x, a45.y, a67.x, a67.y};
                unsigned long long bv[4] = {b01.x, b01.y, b23.x, b23.y};
#pragma unroll
                for (int m = 0; m < 8; m++)
#pragma unroll
                    for (int p = 0; p < 4; p++)
                        asm("fma.rn.f32x2 %0, %1, %2, %0;"
                            : "+l"(acc[m][p]) : "l"(av[m]), "l"(bv[p]));
            }
            __syncthreads();
        }
    }

    float bsum[8];
#pragma unroll
    for (int j = 0; j < 8; j++) {
        int c = tx * 8 + j;
        bsum[j] = bias[c] + bias[DIM + c] + bias[2 * DIM + c]
                + bias[3 * DIM + c] + bias[4 * DIM + c];
    }
#pragma unroll
    for (int m = 0; m < 8; m++) {
        int gr = m0 + ty * 8 + m;
        if (gr >= NN) continue;
        float* row = C + (size_t)gr * DIM + tx * 8;
        *(float4*)(row)     = make_float4(lo32(acc[m][0]) + bsum[0],
                                          hi32(acc[m][0]) + bsum[1],
                                          lo32(acc[m][1]) + bsum[2],
                                          hi32(acc[m][1]) + bsum[3]);
        *(float4*)(row + 4) = make_float4(lo32(acc[m][2]) + bsum[4],
                                          hi32(acc[m][2]) + bsum[5],
                                          lo32(acc[m][3]) + bsum[6],
                                          hi32(acc[m][3]) + bsum[7]);
    }
}

// ---------------- fusion + classifier (FFMA2) --------------------------------
// out = (w0*relu(acc0) + w1*relu(acc1)) @ Wc + bc
__global__ void __launch_bounds__(256, 2) k_final(const float* __restrict__ fw,
                                                  const float* __restrict__ Wc,
                                                  const float* __restrict__ bc,
                                                  float* __restrict__ out) {
    __shared__ float AsD[32][256];
    __shared__ float Bs [32][64];
    int tid = threadIdx.x;
    int tx  = tid & 15;              // cols tx*4 .. tx*4+3
    int ty  = tid >> 4;              // rows ty*8 .. ty*8+7
    int m0  = blockIdx.x * 128;

    float f0 = fw[0], f1 = fw[1];
    float mx = fmaxf(f0, f1);
    float e0 = __expf(f0 - mx), e1 = __expf(f1 - mx);
    float w0 = e0 / (e0 + e1), w1 = 1.0f - w0;

    unsigned long long acc[8][2];
#pragma unroll
    for (int m = 0; m < 8; m++) { acc[m][0] = 0ull; acc[m][1] = 0ull; }

    for (int k0 = 0; k0 < DIM; k0 += 32) {
#pragma unroll
        for (int l = 0; l < 4; l++) {
            int f  = tid + l * 256;
            int r  = f & 127;
            int kv = f >> 7;
            float4 h = make_float4(0.f, 0.f, 0.f, 0.f);
            int gr = m0 + r;
            if (gr < NN) {
                size_t off = (size_t)gr * DIM + k0 + kv * 4;
                float4 a0 = *(const float4*)(g_acc0 + off);
                float4 a1 = *(const float4*)(g_acc1 + off);
                h.x = w0 * fmaxf(a0.x, 0.f) + w1 * fmaxf(a1.x, 0.f);
                h.y = w0 * fmaxf(a0.y, 0.f) + w1 * fmaxf(a1.y, 0.f);
                h.z = w0 * fmaxf(a0.z, 0.f) + w1 * fmaxf(a1.z, 0.f);
                h.w = w0 * fmaxf(a0.w, 0.f) + w1 * fmaxf(a1.w, 0.f);
            }
            *(float2*)&AsD[kv * 4 + 0][2 * r] = make_float2(h.x, h.x);
            *(float2*)&AsD[kv * 4 + 1][2 * r] = make_float2(h.y, h.y);
            *(float2*)&AsD[kv * 4 + 2][2 * r] = make_float2(h.z, h.z);
            *(float2*)&AsD[kv * 4 + 3][2 * r] = make_float2(h.w, h.w);
        }
#pragma unroll
        for (int l = 0; l < 2; l++) {
            int f  = tid + l * 256;
            int k  = f >> 4;
            int cv = f & 15;
            *(float4*)&Bs[k][cv * 4] = *(const float4*)(Wc + (size_t)(k0 + k) * OUTD + cv * 4);
        }
        __syncthreads();

#pragma unroll
        for (int k = 0; k < 32; k++) {
            ulonglong2 a01 = *(const ulonglong2*)&AsD[k][ty * 16 + 0];
            ulonglong2 a23 = *(const ulonglong2*)&AsD[k][ty * 16 + 4];
            ulonglong2 a45 = *(const ulonglong2*)&AsD[k][ty * 16 + 8];
            ulonglong2 a67 = *(const ulonglong2*)&AsD[k][ty * 16 + 12];
            ulonglong2 b01 = *(const ulonglong2*)&Bs[k][tx * 4];
            unsigned long long av[8] = {a01.x, a01.y, a23.x, a23.y,
                                        a45.x, a45.y, a67.x, a67.y};
            unsigned long long bv[2] = {b01.x, b01.y};
#pragma unroll
            for (int m = 0; m < 8; m++)
#pragma unroll
                for (int p = 0; p < 2; p++)
                    asm("fma.rn.f32x2 %0, %1, %2, %0;"
                        : "+l"(acc[m][p]) : "l"(av[m]), "l"(bv[p]));
        }
        __syncthreads();
    }

    float4 bb = *(const float4*)(bc + tx * 4);
#pragma unroll
    for (int m = 0; m < 8; m++) {
        int gr = m0 + ty * 8 + m;
        if (gr >= NN) continue;
        float4 o;
        o.x = lo32(acc[m][0]) + bb.x;
        o.y = hi32(acc[m][0]) + bb.y;
        o.z = lo32(acc[m][1]) + bb.z;
        o.w = hi32(acc[m][1]) + bb.w;
        *(float4*)(out + (size_t)gr * OUTD + tx * 4) = o;
    }
}

// ---------------- host orchestration ---------------------------------------
extern "C" void kernel_launch(void* const* d_in, const int* in_sizes, int n_in,
                              void* d_out, int out_size) {
    const float* x      = (const float*)d_in[0];
    const int*   ei     = (const int*)d_in[1];
    const int*   gei    = (const int*)d_in[2];
    const float* w_orig = (const float*)d_in[3];
    const float* b_orig = (const float*)d_in[4];
    const float* w_aug  = (const float*)d_in[5];
    const float* b_aug  = (const float*)d_in[6];
    const float* fw     = (const float*)d_in[7];
    const float* clfw   = (const float*)d_in[8];
    const float* clfb   = (const float*)d_in[9];
    float*       out    = (float*)d_out;

    float *acc0, *acc1, *bufA, *bufB, *bufC, *bufD;
    cudaGetSymbolAddress((void**)&acc0, g_acc0);
    cudaGetSymbolAddress((void**)&acc1, g_acc1);
    cudaGetSymbolAddress((void**)&bufA, g_bufA);
    cudaGetSymbolAddress((void**)&bufB, g_bufB);
    cudaGetSymbolAddress((void**)&bufC, g_bufC);
    cudaGetSymbolAddress((void**)&bufD, g_bufD);

    const int TB = 256;
    dim3 gN((NN + TB - 1) / TB);
    dim3 gE((EE + TB - 1) / TB);
    dim3 gP((NN * 32 + TB - 1) / TB);        // pull: 1 warp/node

    for (int g = 0; g < 2; g++) {
        const int*   edges = g ? gei : ei;
        const float* W     = g ? w_aug : w_orig;
        const float* b     = g ? b_aug : b_orig;
        float*       acc   = g ? acc1  : acc0;

        // CSR build (deg_fin fused into scan1)
        k_deg_init <<<gN, TB>>>();
        k_deg_count<<<gE, TB>>>(edges);
        k_scan1<<<NB_SCAN, 512>>>();
        k_scan2<<<1, 256>>>();
        k_scan3<<<gN, TB>>>();
        k_fill <<<gE, TB>>>(edges);

        // hop chain: Tx1..Tx4 into four buffers
        k_pull<<<gP, TB>>>(x,    bufA);
        k_pull<<<gP, TB>>>(bufA, bufB);
        k_pull<<<gP, TB>>>(bufB, bufC);
        k_pull<<<gP, TB>>>(bufC, bufD);

        // one fused GEMM per branch: acc = sum_s Tx_s @ W_s + sum bias
        k_gemm5<<<GEMM_BLKS, TB>>>(x, bufA, bufB, bufC, bufD, W, acc, b);
    }

    k_final<<<GEMM_BLKS, TB>>>(fw, clfw, clfb, out);
}

// round 16
// speedup vs baseline: 2.2672x; 1.4164x over previous
#include <cuda_runtime.h>
#include <cuda_bf16.h>
#include <cstdint>

#define NN   100000
#define EE   1600000
#define DIM  128
#define OUTD 64
#define NB_SCAN 196      // ceil(NN/512)
#define GEMM_BLKS 782    // ceil(NN/128)

// ---------------- scratch (device globals; no allocation allowed) ----------
__device__ float g_dinv[NN];
__device__ int   g_cnt[NN];
__device__ int   g_off[NN + 1];
__device__ int   g_cur[NN];
__device__ int   g_bsum[256];
__device__ int2  g_adj[EE];                  // (src_row, scale_as_float_bits)
__device__ float g_acc0[(size_t)NN * DIM];
__device__ float g_acc1[(size_t)NN * DIM];
__device__ float g_bufA[(size_t)NN * DIM];
__device__ float g_bufB[(size_t)NN * DIM];
__device__ float g_bufC[(size_t)NN * DIM];
__device__ float g_bufD[(size_t)NN * DIM];

__device__ __forceinline__ float lo32(unsigned long long u) {
    return __uint_as_float((unsigned)u);
}
__device__ __forceinline__ float hi32(unsigned long long u) {
    return __uint_as_float((unsigned)(u >> 32));
}

// ---------------- degree -----------------------------------------------------
__global__ void k_deg_init() {
    int i = blockIdx.x * blockDim.x + threadIdx.x;
    if (i < NN) g_cnt[i] = 0;
}
__global__ void k_deg_count(const int* __restrict__ ei) {
    int i = blockIdx.x * blockDim.x + threadIdx.x;
    if (i < EE) atomicAdd(&g_cnt[ei[EE + i]], 1);
}

// ---------------- scan1 (+ deg_fin fused) ------------------------------------
__global__ void k_scan1() {               // 512 threads per block
    __shared__ int s[512];
    int t = threadIdx.x;
    int i = blockIdx.x * 512 + t;
    int v = (i < NN) ? g_cnt[i] : 0;
    s[t] = v;
    __syncthreads();
#pragma unroll
    for (int off = 1; off < 512; off <<= 1) {
        int u = (t >= off) ? s[t - off] : 0;
        __syncthreads();
        s[t] += u;
        __syncthreads();
    }
    if (i < NN) {
        g_off[i] = s[t] - v;
        g_cur[i] = 0;
        g_dinv[i] = rsqrtf((float)v + 1.0f);   // +1 self loop
    }
    if (t == 511) g_bsum[blockIdx.x] = s[511];
}
__global__ void k_scan2() {               // 1 block, 256 threads
    __shared__ int s[256];
    int t = threadIdx.x;
    int v = (t < NB_SCAN) ? g_bsum[t] : 0;
    s[t] = v;
    __syncthreads();
#pragma unroll
    for (int off = 1; off < 256; off <<= 1) {
        int u = (t >= off) ? s[t - off] : 0;
        __syncthreads();
        s[t] += u;
        __syncthreads();
    }
    if (t < NB_SCAN) g_bsum[t] = s[t] - v;
}
__global__ void k_scan3() {
    int i = blockIdx.x * blockDim.x + threadIdx.x;
    if (i < NN) g_off[i] += g_bsum[i >> 9];
    if (i == 0) g_off[NN] = EE;
}

// ---------------- CSR fill ---------------------------------------------------
__global__ void k_fill(const int* __restrict__ ei) {
    int i = blockIdx.x * blockDim.x + threadIdx.x;
    if (i >= EE) return;
    int r = ei[i];
    int c = ei[EE + i];
    int pos = g_off[c] + atomicAdd(&g_cur[c], 1);
    float s = g_dinv[r] * g_dinv[c];
    g_adj[pos] = make_int2(r, __float_as_int(s));
}

// ---------------- hop: CSR pull (one warp per node, self-loop fused) ---------
__global__ void k_pull(const float* __restrict__ src, float* __restrict__ dst) {
    int w = (blockIdx.x * blockDim.x + threadIdx.x) >> 5;
    if (w >= NN) return;
    int lane = threadIdx.x & 31;
    int beg = g_off[w];
    int end = g_off[w + 1];
    float d = g_dinv[w];
    float dd = d * d;
    float4 acc = ((const float4*)(src + (size_t)w * DIM))[lane];
    acc.x *= dd; acc.y *= dd; acc.z *= dd; acc.w *= dd;
#pragma unroll 4
    for (int j = beg; j < end; j++) {
        int2 e = __ldg(&g_adj[j]);
        float s = __int_as_float(e.y);
        float4 v = ((const float4*)(src + (size_t)e.x * DIM))[lane];
        acc.x += s * v.x; acc.y += s * v.y;
        acc.z += s * v.z; acc.w += s * v.w;
    }
    ((float4*)(dst + (size_t)w * DIM))[lane] = acc;
}

// ---------------- mma.sync helper --------------------------------------------
__device__ __forceinline__ void mma16816(float* c, const uint32_t* a,
                                         const uint32_t* b) {
    asm volatile(
        "mma.sync.aligned.m16n8k16.row.col.f32.bf16.bf16.f32 "
        "{%0,%1,%2,%3}, {%4,%5,%6,%7}, {%8,%9}, {%0,%1,%2,%3};"
        : "+f"(c[0]), "+f"(c[1]), "+f"(c[2]), "+f"(c[3])
        : "r"(a[0]), "r"(a[1]), "r"(a[2]), "r"(a[3]), "r"(b[0]), "r"(b[1]));
}
__device__ __forceinline__ uint32_t pack_bf16x2(float x, float y) {
    __nv_bfloat162 p;
    p.x = __float2bfloat16(x);
    p.y = __float2bfloat16(y);
    return *(uint32_t*)&p;
}

// ---------------- tensor 5-source GEMM (legacy HMMA, bf16 hi/lo split) -------
// C[128-tile][128] = sum_s A_s * W_s + sum bias.
// 256 thr = 8 warps (2m x 4n); warp tile 64x32; BK=32; K=640 over 20 chunks.
// Fragments loaded with plain b32 smem loads (row stride 40 -> conflict-free).
#define ASTRIDE 40
__global__ void __launch_bounds__(256) k_gemm5_mma(
    const float* __restrict__ A0, const float* __restrict__ A1,
    const float* __restrict__ A2, const float* __restrict__ A3,
    const float* __restrict__ A4, const float* __restrict__ W,
    float* __restrict__ C, const float* __restrict__ bias) {
    __shared__ __align__(16) __nv_bfloat16 As[2][128][ASTRIDE];  // hi/lo
    __shared__ __align__(16) __nv_bfloat16 Bs[2][128][ASTRIDE];  // [n][k] hi/lo
    int tid  = threadIdx.x;
    int wid  = tid >> 5;
    int lane = tid & 31;
    int lq   = lane >> 2;            // 0..7
    int kp   = lane & 3;             // 0..3
    int wm0  = (wid >> 2) * 64;      // warp m origin (0 or 64)
    int wn0  = (wid & 3) * 32;       // warp n origin (0,32,64,96)
    int m0   = blockIdx.x * 128;

    float c[4][4][4];                // [mt][nt][frag]
#pragma unroll
    for (int mt = 0; mt < 4; mt++)
#pragma unroll
        for (int nt = 0; nt < 4; nt++)
#pragma unroll
            for (int q = 0; q < 4; q++) c[mt][nt][q] = 0.0f;

    for (int ch = 0; ch < 20; ch++) {
        int s  = ch >> 2;            // source 0..4
        int k0 = (ch & 3) * 32;      // k offset within source
        const float* A = (s == 0) ? A0 : (s == 1) ? A1 : (s == 2) ? A2
                       : (s == 3) ? A3 : A4;
        const float* B = W + (size_t)s * DIM * DIM;

        // A tile: 128 rows x 32 k (1024 float4), hi/lo split
#pragma unroll
        for (int l = 0; l < 4; l++) {
            int f  = tid + l * 256;
            int r  = f >> 3;             // 0..127
            int kv = f & 7;              // float4 index within 32 k
            float4 v = make_float4(0.f, 0.f, 0.f, 0.f);
            int gr = m0 + r;
            if (gr < NN) v = *(const float4*)(A + (size_t)gr * DIM + k0 + kv * 4);
            __nv_bfloat16 hx = __float2bfloat16(v.x), hy = __float2bfloat16(v.y);
            __nv_bfloat16 hz = __float2bfloat16(v.z), hw = __float2bfloat16(v.w);
            uint32_t h0 = pack_bf16x2(v.x, v.y);
            uint32_t h1 = pack_bf16x2(v.z, v.w);
            uint32_t l0 = pack_bf16x2(v.x - __bfloat162float(hx),
                                      v.y - __bfloat162float(hy));
            uint32_t l1 = pack_bf16x2(v.z - __bfloat162float(hz),
                                      v.w - __bfloat162float(hw));
            uint32_t* ph = (uint32_t*)&As[0][r][kv * 4];
            uint32_t* pl = (uint32_t*)&As[1][r][kv * 4];
            ph[0] = h0; ph[1] = h1;
            pl[0] = l0; pl[1] = l1;
        }
        // B tile: W[k][n] -> Bs[n][k] transpose; scalar coalesced loads
#pragma unroll
        for (int l = 0; l < 16; l++) {
            int f = tid + l * 256;       // 0..4095
            int n = f & 127;
            int k = f >> 7;              // 0..31
            float v = B[(size_t)(k0 + k) * DIM + n];
            __nv_bfloat16 h = __float2bfloat16(v);
            Bs[0][n][k] = h;
            Bs[1][n][k] = __float2bfloat16(v - __bfloat162float(h));
        }
        __syncthreads();

#pragma unroll
        for (int kk = 0; kk < 32; kk += 16) {
            // b fragments for this warp's 4 n8-tiles (hi & lo)
            uint32_t bh[4][2], bl[4][2];
#pragma unroll
            for (int nt = 0; nt < 4; nt++) {
                const __nv_bfloat16* bp = &Bs[0][wn0 + nt * 8 + lq][kk + kp * 2];
                bh[nt][0] = *(const uint32_t*)bp;
                bh[nt][1] = *(const uint32_t*)(bp + 8);
                const __nv_bfloat16* bq = &Bs[1][wn0 + nt * 8 + lq][kk + kp * 2];
                bl[nt][0] = *(const uint32_t*)bq;
                bl[nt][1] = *(const uint32_t*)(bq + 8);
            }
#pragma unroll
            for (int mt = 0; mt < 4; mt++) {
                const __nv_bfloat16* ap = &As[0][wm0 + mt * 16 + lq][kk + kp * 2];
                uint32_t ah[4], al[4];
                ah[0] = *(const uint32_t*)ap;
                ah[1] = *(const uint32_t*)(ap + 8 * ASTRIDE);
                ah[2] = *(const uint32_t*)(ap + 8);
                ah[3] = *(const uint32_t*)(ap + 8 * ASTRIDE + 8);
                const __nv_bfloat16* aq = &As[1][wm0 + mt * 16 + lq][kk + kp * 2];
                al[0] = *(const uint32_t*)aq;
                al[1] = *(const uint32_t*)(aq + 8 * ASTRIDE);
                al[2] = *(const uint32_t*)(aq + 8);
                al[3] = *(const uint32_t*)(aq + 8 * ASTRIDE + 8);
#pragma unroll
                for (int nt = 0; nt < 4; nt++) {
                    mma16816(c[mt][nt], ah, bh[nt]);   // hi*hi
                    mma16816(c[mt][nt], ah, bl[nt]);   // hi*lo
                    mma16816(c[mt][nt], al, bh[nt]);   // lo*hi
                }
            }
        }
        __syncthreads();
    }

    // bias column sums for this thread's columns (2 per n8 tile)
    float2 bs[4];
#pragma unroll
    for (int nt = 0; nt < 4; nt++) {
        int col = wn0 + nt * 8 + kp * 2;
        bs[nt].x = bias[col] + bias[DIM + col] + bias[2 * DIM + col]
                 + bias[3 * DIM + col] + bias[4 * DIM + col];
        bs[nt].y = bias[col + 1] + bias[DIM + col + 1] + bias[2 * DIM + col + 1]
                 + bias[3 * DIM + col + 1] + bias[4 * DIM + col + 1];
    }
    // writeback: c0,c1 -> row lq; c2,c3 -> row lq+8
#pragma unroll
    for (int mt = 0; mt < 4; mt++) {
        int gr0 = m0 + wm0 + mt * 16 + lq;
        int gr1 = gr0 + 8;
#pragma unroll
        for (int nt = 0; nt < 4; nt++) {
            int col = wn0 + nt * 8 + kp * 2;
            if (gr0 < NN)
                *(float2*)(C + (size_t)gr0 * DIM + col) =
                    make_float2(c[mt][nt][0] + bs[nt].x, c[mt][nt][1] + bs[nt].y);
            if (gr1 < NN)
                *(float2*)(C + (size_t)gr1 * DIM + col) =
                    make_float2(c[mt][nt][2] + bs[nt].x, c[mt][nt][3] + bs[nt].y);
        }
    }
}

// ---------------- fusion + classifier (FFMA2) --------------------------------
// out = (w0*relu(acc0) + w1*relu(acc1)) @ Wc + bc
__global__ void __launch_bounds__(256, 2) k_final(const float* __restrict__ fw,
                                                  const float* __restrict__ Wc,
                                                  const float* __restrict__ bc,
                                                  float* __restrict__ out) {
    __shared__ float AsD[32][256];
    __shared__ float Bs [32][64];
    int tid = threadIdx.x;
    int tx  = tid & 15;              // cols tx*4 .. tx*4+3
    int ty  = tid >> 4;              // rows ty*8 .. ty*8+7
    int m0  = blockIdx.x * 128;

    float f0 = fw[0], f1 = fw[1];
    float mx = fmaxf(f0, f1);
    float e0 = __expf(f0 - mx), e1 = __expf(f1 - mx);
    float w0 = e0 / (e0 + e1), w1 = 1.0f - w0;

    unsigned long long acc[8][2];
#pragma unroll
    for (int m = 0; m < 8; m++) { acc[m][0] = 0ull; acc[m][1] = 0ull; }

    for (int k0 = 0; k0 < DIM; k0 += 32) {
#pragma unroll
        for (int l = 0; l < 4; l++) {
            int f  = tid + l * 256;
            int r  = f & 127;
            int kv = f >> 7;
            float4 h = make_float4(0.f, 0.f, 0.f, 0.f);
            int gr = m0 + r;
            if (gr < NN) {
                size_t off = (size_t)gr * DIM + k0 + kv * 4;
                float4 a0 = *(const float4*)(g_acc0 + off);
                float4 a1 = *(const float4*)(g_acc1 + off);
                h.x = w0 * fmaxf(a0.x, 0.f) + w1 * fmaxf(a1.x, 0.f);
                h.y = w0 * fmaxf(a0.y, 0.f) + w1 * fmaxf(a1.y, 0.f);
                h.z = w0 * fmaxf(a0.z, 0.f) + w1 * fmaxf(a1.z, 0.f);
                h.w = w0 * fmaxf(a0.w, 0.f) + w1 * fmaxf(a1.w, 0.f);
            }
            *(float2*)&AsD[kv * 4 + 0][2 * r] = make_float2(h.x, h.x);
            *(float2*)&AsD[kv * 4 + 1][2 * r] = make_float2(h.y, h.y);
            *(float2*)&AsD[kv * 4 + 2][2 * r] = make_float2(h.z, h.z);
            *(float2*)&AsD[kv * 4 + 3][2 * r] = make_float2(h.w, h.w);
        }
#pragma unroll
        for (int l = 0; l < 2; l++) {
            int f  = tid + l * 256;
            int k  = f >> 4;
            int cv = f & 15;
            *(float4*)&Bs[k][cv * 4] = *(const float4*)(Wc + (size_t)(k0 + k) * OUTD + cv * 4);
        }
        __syncthreads();

#pragma unroll
        for (int k = 0; k < 32; k++) {
            ulonglong2 a01 = *(const ulonglong2*)&AsD[k][ty * 16 + 0];
            ulonglong2 a23 = *(const ulonglong2*)&AsD[k][ty * 16 + 4];
            ulonglong2 a45 = *(const ulonglong2*)&AsD[k][ty * 16 + 8];
            ulonglong2 a67 = *(const ulonglong2*)&AsD[k][ty * 16 + 12];
            ulonglong2 b01 = *(const ulonglong2*)&Bs[k][tx * 4];
            unsigned long long av[8] = {a01.x, a01.y, a23.x, a23.y,
                                        a45.x, a45.y, a67.x, a67.y};
            unsigned long long bv[2] = {b01.x, b01.y};
#pragma unroll
            for (int m = 0; m < 8; m++)
#pragma unroll
                for (int p = 0; p < 2; p++)
                    asm("fma.rn.f32x2 %0, %1, %2, %0;"
                        : "+l"(acc[m][p]) : "l"(av[m]), "l"(bv[p]));
        }
        __syncthreads();
    }

    float4 bb = *(const float4*)(bc + tx * 4);
#pragma unroll
    for (int m = 0; m < 8; m++) {
        int gr = m0 + ty * 8 + m;
        if (gr >= NN) continue;
        float4 o;
        o.x = lo32(acc[m][0]) + bb.x;
        o.y = hi32(acc[m][0]) + bb.y;
        o.z = lo32(acc[m][1]) + bb.z;
        o.w = hi32(acc[m][1]) + bb.w;
        *(float4*)(out + (size_t)gr * OUTD + tx * 4) = o;
    }
}

// ---------------- host orchestration ---------------------------------------
extern "C" void kernel_launch(void* const* d_in, const int* in_sizes, int n_in,
                              void* d_out, int out_size) {
    const float* x      = (const float*)d_in[0];
    const int*   ei     = (const int*)d_in[1];
    const int*   gei    = (const int*)d_in[2];
    const float* w_orig = (const float*)d_in[3];
    const float* b_orig = (const float*)d_in[4];
    const float* w_aug  = (const float*)d_in[5];
    const float* b_aug  = (const float*)d_in[6];
    const float* fw     = (const float*)d_in[7];
    const float* clfw   = (const float*)d_in[8];
    const float* clfb   = (const float*)d_in[9];
    float*       out    = (float*)d_out;

    float *acc0, *acc1, *bufA, *bufB, *bufC, *bufD;
    cudaGetSymbolAddress((void**)&acc0, g_acc0);
    cudaGetSymbolAddress((void**)&acc1, g_acc1);
    cudaGetSymbolAddress((void**)&bufA, g_bufA);
    cudaGetSymbolAddress((void**)&bufB, g_bufB);
    cudaGetSymbolAddress((void**)&bufC, g_bufC);
    cudaGetSymbolAddress((void**)&bufD, g_bufD);

    const int TB = 256;
    dim3 gN((NN + TB - 1) / TB);
    dim3 gE((EE + TB - 1) / TB);
    dim3 gP((NN * 32 + TB - 1) / TB);        // pull: 1 warp/node

    for (int g = 0; g < 2; g++) {
        const int*   edges = g ? gei : ei;
        const float* W     = g ? w_aug : w_orig;
        const float* b     = g ? b_aug : b_orig;
        float*       acc   = g ? acc1  : acc0;

        // CSR build (deg_fin fused into scan1)
        k_deg_init <<<gN, TB>>>();
        k_deg_count<<<gE, TB>>>(edges);
        k_scan1<<<NB_SCAN, 512>>>();
        k_scan2<<<1, 256>>>();
        k_scan3<<<gN, TB>>>();
        k_fill <<<gE, TB>>>(edges);

        // hop chain: Tx1..Tx4
        k_pull<<<gP, TB>>>(x,    bufA);
        k_pull<<<gP, TB>>>(bufA, bufB);
        k_pull<<<gP, TB>>>(bufB, bufC);
        k_pull<<<gP, TB>>>(bufC, bufD);

        // HMMA fused GEMM: acc = sum_s Tx_s @ W_s + sum bias
        k_gemm5_mma<<<GEMM_BLKS, TB>>>(x, bufA, bufB, bufC, bufD, W, acc, b);
    }

    k_final<<<GEMM_BLKS, TB>>>(fw, clfw, clfb, out);
}

// round 17
// speedup vs baseline: 2.5872x; 1.1412x over previous
#include <cuda_runtime.h>
#include <cuda_bf16.h>
#include <cstdint>

#define NN   100000
#define EE   1600000
#define DIM  128
#define OUTD 64
#define NB_SCAN 196      // ceil(NN/512)
#define GEMM_BLKS 782    // ceil(NN/128)

// ---------------- scratch (device globals; no allocation allowed) ----------
__device__ float g_dinv[NN];
__device__ int   g_cnt[NN];
__device__ int   g_off[NN + 1];
__device__ int   g_cur[NN];
__device__ int   g_bsum[256];
__device__ int2  g_adj[EE];                  // (src_row, scale_as_float_bits)
__device__ float g_acc0[(size_t)NN * DIM];
__device__ float g_bufA[(size_t)NN * DIM];
__device__ float g_bufB[(size_t)NN * DIM];
__device__ float g_bufC[(size_t)NN * DIM];
__device__ float g_bufD[(size_t)NN * DIM];

// ---------------- degree (init fused into scan1 of previous pass) -----------
__global__ void k_deg_count(const int* __restrict__ ei) {
    int i = blockIdx.x * blockDim.x + threadIdx.x;
    if (i < EE) atomicAdd(&g_cnt[ei[EE + i]], 1);
}

// ---------------- scan1 (+ deg_fin fused, + g_cnt re-zero for next pass) ----
__global__ void k_scan1() {               // 512 threads per block
    __shared__ int s[512];
    int t = threadIdx.x;
    int i = blockIdx.x * 512 + t;
    int v = (i < NN) ? g_cnt[i] : 0;
    s[t] = v;
    __syncthreads();
#pragma unroll
    for (int off = 1; off < 512; off <<= 1) {
        int u = (t >= off) ? s[t - off] : 0;
        __syncthreads();
        s[t] += u;
        __syncthreads();
    }
    if (i < NN) {
        g_off[i] = s[t] - v;
        g_cur[i] = 0;
        g_cnt[i] = 0;                          // re-zero for the next pass/replay
        g_dinv[i] = rsqrtf((float)v + 1.0f);   // +1 self loop
    }
    if (t == 511) g_bsum[blockIdx.x] = s[511];
}
__global__ void k_scan2() {               // 1 block, 256 threads
    __shared__ int s[256];
    int t = threadIdx.x;
    int v = (t < NB_SCAN) ? g_bsum[t] : 0;
    s[t] = v;
    __syncthreads();
#pragma unroll
    for (int off = 1; off < 256; off <<= 1) {
        int u = (t >= off) ? s[t - off] : 0;
        __syncthreads();
        s[t] += u;
        __syncthreads();
    }
    if (t < NB_SCAN) g_bsum[t] = s[t] - v;
}
__global__ void k_scan3() {
    int i = blockIdx.x * blockDim.x + threadIdx.x;
    if (i < NN) g_off[i] += g_bsum[i >> 9];
    if (i == 0) g_off[NN] = EE;
}

// ---------------- CSR fill ---------------------------------------------------
__global__ void k_fill(const int* __restrict__ ei) {
    int i = blockIdx.x * blockDim.x + threadIdx.x;
    if (i >= EE) return;
    int r = ei[i];
    int c = ei[EE + i];
    int pos = g_off[c] + atomicAdd(&g_cur[c], 1);
    float s = g_dinv[r] * g_dinv[c];
    g_adj[pos] = make_int2(r, __float_as_int(s));
}

// ---------------- hop: CSR pull (one warp per node, self-loop fused) ---------
__global__ void k_pull(const float* __restrict__ src, float* __restrict__ dst) {
    int w = (blockIdx.x * blockDim.x + threadIdx.x) >> 5;
    if (w >= NN) return;
    int lane = threadIdx.x & 31;
    int beg = g_off[w];
    int end = g_off[w + 1];
    float d = g_dinv[w];
    float dd = d * d;
    float4 acc = ((const float4*)(src + (size_t)w * DIM))[lane];
    acc.x *= dd; acc.y *= dd; acc.z *= dd; acc.w *= dd;
#pragma unroll 4
    for (int j = beg; j < end; j++) {
        int2 e = __ldg(&g_adj[j]);
        float s = __int_as_float(e.y);
        float4 v = ((const float4*)(src + (size_t)e.x * DIM))[lane];
        acc.x += s * v.x; acc.y += s * v.y;
        acc.z += s * v.z; acc.w += s * v.w;
    }
    ((float4*)(dst + (size_t)w * DIM))[lane] = acc;
}

// ---------------- mma.sync helpers -------------------------------------------
__device__ __forceinline__ void mma16816(float* c, const uint32_t* a,
                                         const uint32_t* b) {
    asm volatile(
        "mma.sync.aligned.m16n8k16.row.col.f32.bf16.bf16.f32 "
        "{%0,%1,%2,%3}, {%4,%5,%6,%7}, {%8,%9}, {%0,%1,%2,%3};"
        : "+f"(c[0]), "+f"(c[1]), "+f"(c[2]), "+f"(c[3])
        : "r"(a[0]), "r"(a[1]), "r"(a[2]), "r"(a[3]), "r"(b[0]), "r"(b[1]));
}
__device__ __forceinline__ uint32_t pack_bf16x2(float x, float y) {
    __nv_bfloat162 p;
    p.x = __float2bfloat16(x);
    p.y = __float2bfloat16(y);
    return *(uint32_t*)&p;
}
__device__ __forceinline__ void split_bf16(float v, __nv_bfloat16& h, __nv_bfloat16& l) {
    h = __float2bfloat16(v);
    l = __float2bfloat16(v - __bfloat162float(h));
}

// ---------------- tensor 5-source GEMM (+ optional fused classifier) ---------
// mainloop: c = sum_s A_s * W_s   (bf16 hi/lo 3-product split, 20 K-chunks)
// mode 0 (outp==null): C = relu(c + bias_sum)
// mode 1: h = w0*accOther + w1*relu(c + bias_sum); out = h @ Wc + bc  (HMMA)
#define ASTRIDE 40
#define HSTRIDE 136
#define SMEM_MMA 104448
__global__ void __launch_bounds__(256) k_gemm5_mma(
    const float* __restrict__ A0, const float* __restrict__ A1,
    const float* __restrict__ A2, const float* __restrict__ A3,
    const float* __restrict__ A4, const float* __restrict__ W,
    float* __restrict__ C, const float* __restrict__ bias,
    const float* __restrict__ accOther, const float* __restrict__ fw,
    const float* __restrict__ Wc, const float* __restrict__ bc,
    float* __restrict__ outp) {
    extern __shared__ __align__(16) char dsm[];
    __nv_bfloat16 (*Ah)[ASTRIDE] = reinterpret_cast<__nv_bfloat16(*)[ASTRIDE]>(dsm);
    __nv_bfloat16 (*Al)[ASTRIDE] = reinterpret_cast<__nv_bfloat16(*)[ASTRIDE]>(dsm + 10240);
    __nv_bfloat16 (*Bh)[ASTRIDE] = reinterpret_cast<__nv_bfloat16(*)[ASTRIDE]>(dsm + 20480);
    __nv_bfloat16 (*Bl)[ASTRIDE] = reinterpret_cast<__nv_bfloat16(*)[ASTRIDE]>(dsm + 30720);
    // epilogue overlay (valid only after the final mainloop __syncthreads)
    __nv_bfloat16 (*Hh)[HSTRIDE] = reinterpret_cast<__nv_bfloat16(*)[HSTRIDE]>(dsm);
    __nv_bfloat16 (*Hl)[HSTRIDE] = reinterpret_cast<__nv_bfloat16(*)[HSTRIDE]>(dsm + 34816);
    __nv_bfloat16 (*Wh)[HSTRIDE] = reinterpret_cast<__nv_bfloat16(*)[HSTRIDE]>(dsm + 69632);
    __nv_bfloat16 (*Wl)[HSTRIDE] = reinterpret_cast<__nv_bfloat16(*)[HSTRIDE]>(dsm + 87040);

    int tid  = threadIdx.x;
    int wid  = tid >> 5;
    int lane = tid & 31;
    int lq   = lane >> 2;            // 0..7
    int kp   = lane & 3;             // 0..3
    int wm0  = (wid >> 2) * 64;      // warp m origin (0 or 64)
    int wn0  = (wid & 3) * 32;       // warp n origin (0,32,64,96)
    int m0   = blockIdx.x * 128;

    float c[4][4][4];                // [mt][nt][frag]
#pragma unroll
    for (int mt = 0; mt < 4; mt++)
#pragma unroll
        for (int nt = 0; nt < 4; nt++)
#pragma unroll
            for (int q = 0; q < 4; q++) c[mt][nt][q] = 0.0f;

    for (int ch = 0; ch < 20; ch++) {
        int s  = ch >> 2;
        int k0 = (ch & 3) * 32;
        const float* A = (s == 0) ? A0 : (s == 1) ? A1 : (s == 2) ? A2
                       : (s == 3) ? A3 : A4;
        const float* B = W + (size_t)s * DIM * DIM;

        // A tile: 128 rows x 32 k, hi/lo split
#pragma unroll
        for (int l = 0; l < 4; l++) {
            int f  = tid + l * 256;
            int r  = f >> 3;
            int kv = f & 7;
            float4 v = make_float4(0.f, 0.f, 0.f, 0.f);
            int gr = m0 + r;
            if (gr < NN) v = *(const float4*)(A + (size_t)gr * DIM + k0 + kv * 4);
            __nv_bfloat16 hx = __float2bfloat16(v.x), hy = __float2bfloat16(v.y);
            __nv_bfloat16 hz = __float2bfloat16(v.z), hw = __float2bfloat16(v.w);
            uint32_t h0 = pack_bf16x2(v.x, v.y);
            uint32_t h1 = pack_bf16x2(v.z, v.w);
            uint32_t l0 = pack_bf16x2(v.x - __bfloat162float(hx),
                                      v.y - __bfloat162float(hy));
            uint32_t l1 = pack_bf16x2(v.z - __bfloat162float(hz),
                                      v.w - __bfloat162float(hw));
            uint32_t* ph = (uint32_t*)&Ah[r][kv * 4];
            uint32_t* pl = (uint32_t*)&Al[r][kv * 4];
            ph[0] = h0; ph[1] = h1;
            pl[0] = l0; pl[1] = l1;
        }
        // B tile: W[k][n] -> Bs[n][k] transpose
#pragma unroll
        for (int l = 0; l < 16; l++) {
            int f = tid + l * 256;
            int n = f & 127;
            int k = f >> 7;
            float v = B[(size_t)(k0 + k) * DIM + n];
            __nv_bfloat16 h, lo;
            split_bf16(v, h, lo);
            Bh[n][k] = h;
            Bl[n][k] = lo;
        }
        __syncthreads();

#pragma unroll
        for (int kk = 0; kk < 32; kk += 16) {
            uint32_t bh[4][2], bl[4][2];
#pragma unroll
            for (int nt = 0; nt < 4; nt++) {
                const __nv_bfloat16* bp = &Bh[wn0 + nt * 8 + lq][kk + kp * 2];
                bh[nt][0] = *(const uint32_t*)bp;
                bh[nt][1] = *(const uint32_t*)(bp + 8);
                const __nv_bfloat16* bq = &Bl[wn0 + nt * 8 + lq][kk + kp * 2];
                bl[nt][0] = *(const uint32_t*)bq;
                bl[nt][1] = *(const uint32_t*)(bq + 8);
            }
#pragma unroll
            for (int mt = 0; mt < 4; mt++) {
                const __nv_bfloat16* ap = &Ah[wm0 + mt * 16 + lq][kk + kp * 2];
                uint32_t ah[4], al[4];
                ah[0] = *(const uint32_t*)ap;
                ah[1] = *(const uint32_t*)(ap + 8 * ASTRIDE);
                ah[2] = *(const uint32_t*)(ap + 8);
                ah[3] = *(const uint32_t*)(ap + 8 * ASTRIDE + 8);
                const __nv_bfloat16* aq = &Al[wm0 + mt * 16 + lq][kk + kp * 2];
                al[0] = *(const uint32_t*)aq;
                al[1] = *(const uint32_t*)(aq + 8 * ASTRIDE);
                al[2] = *(const uint32_t*)(aq + 8);
                al[3] = *(const uint32_t*)(aq + 8 * ASTRIDE + 8);
#pragma unroll
                for (int nt = 0; nt < 4; nt++) {
                    mma16816(c[mt][nt], ah, bh[nt]);   // hi*hi
                    mma16816(c[mt][nt], ah, bl[nt]);   // hi*lo
                    mma16816(c[mt][nt], al, bh[nt]);   // lo*hi
                }
            }
        }
        __syncthreads();
    }

    // bias column sums for this thread's columns (2 per n8 tile)
    float2 bs[4];
#pragma unroll
    for (int nt = 0; nt < 4; nt++) {
        int col = wn0 + nt * 8 + kp * 2;
        bs[nt].x = bias[col] + bias[DIM + col] + bias[2 * DIM + col]
                 + bias[3 * DIM + col] + bias[4 * DIM + col];
        bs[nt].y = bias[col + 1] + bias[DIM + col + 1] + bias[2 * DIM + col + 1]
                 + bias[3 * DIM + col + 1] + bias[4 * DIM + col + 1];
    }

    if (!outp) {
        // mode 0: C = relu(c + bias_sum)
#pragma unroll
        for (int mt = 0; mt < 4; mt++) {
            int gr0 = m0 + wm0 + mt * 16 + lq;
            int gr1 = gr0 + 8;
#pragma unroll
            for (int nt = 0; nt < 4; nt++) {
                int col = wn0 + nt * 8 + kp * 2;
                if (gr0 < NN)
                    *(float2*)(C + (size_t)gr0 * DIM + col) =
                        make_float2(fmaxf(c[mt][nt][0] + bs[nt].x, 0.f),
                                    fmaxf(c[mt][nt][1] + bs[nt].y, 0.f));
                if (gr1 < NN)
                    *(float2*)(C + (size_t)gr1 * DIM + col) =
                        make_float2(fmaxf(c[mt][nt][2] + bs[nt].x, 0.f),
                                    fmaxf(c[mt][nt][3] + bs[nt].y, 0.f));
            }
        }
        return;
    }

    // ---- mode 1: fused fusion + classifier -----------------------------------
    float f0 = fw[0], f1 = fw[1];
    float mx = fmaxf(f0, f1);
    float e0 = __expf(f0 - mx), e1 = __expf(f1 - mx);
    float w0 = e0 / (e0 + e1), w1 = 1.0f - w0;

    // h = w0*acc0 (pre-relu'd) + w1*relu(c+bias) -> smem hi/lo (epilogue overlay)
#pragma unroll
    for (int mt = 0; mt < 4; mt++) {
        int r0 = wm0 + mt * 16 + lq;
        int r1 = r0 + 8;
        int gr0 = m0 + r0, gr1 = m0 + r1;
#pragma unroll
        for (int nt = 0; nt < 4; nt++) {
            int col = wn0 + nt * 8 + kp * 2;
            float2 p0 = make_float2(0.f, 0.f), p1 = make_float2(0.f, 0.f);
            if (gr0 < NN) p0 = *(const float2*)(accOther + (size_t)gr0 * DIM + col);
            if (gr1 < NN) p1 = *(const float2*)(accOther + (size_t)gr1 * DIM + col);
            float hx0 = w0 * p0.x + w1 * fmaxf(c[mt][nt][0] + bs[nt].x, 0.f);
            float hy0 = w0 * p0.y + w1 * fmaxf(c[mt][nt][1] + bs[nt].y, 0.f);
            float hx1 = w0 * p1.x + w1 * fmaxf(c[mt][nt][2] + bs[nt].x, 0.f);
            float hy1 = w0 * p1.y + w1 * fmaxf(c[mt][nt][3] + bs[nt].y, 0.f);
            __nv_bfloat16 h, lo;
            split_bf16(hx0, h, lo); Hh[r0][col]     = h; Hl[r0][col]     = lo;
            split_bf16(hy0, h, lo); Hh[r0][col + 1] = h; Hl[r0][col + 1] = lo;
            split_bf16(hx1, h, lo); Hh[r1][col]     = h; Hl[r1][col]     = lo;
            split_bf16(hy1, h, lo); Hh[r1][col + 1] = h; Hl[r1][col + 1] = lo;
        }
    }
    // Wc[k][n] (128x64) -> Wh/Wl[n][k] transpose
#pragma unroll
    for (int l = 0; l < 32; l++) {
        int f = tid + l * 256;       // 0..8191
        int n = f & 63;
        int k = f >> 6;              // 0..127
        float v = Wc[(size_t)k * OUTD + n];
        __nv_bfloat16 h, lo;
        split_bf16(v, h, lo);
        Wh[n][k] = h;
        Wl[n][k] = lo;
    }
    __syncthreads();

    // classifier MMA: out[128 x 64] = H @ WcT, K=128
    int cm0 = (wid >> 1) * 32;       // 4 row groups of 32
    int cn0 = (wid & 1) * 32;        // 2 col groups of 32
    float c2[2][4][4];
#pragma unroll
    for (int mt = 0; mt < 2; mt++)
#pragma unroll
        for (int nt = 0; nt < 4; nt++)
#pragma unroll
            for (int q = 0; q < 4; q++) c2[mt][nt][q] = 0.0f;

#pragma unroll
    for (int kk = 0; kk < 128; kk += 16) {
        uint32_t bh[4][2], bl[4][2];
#pragma unroll
        for (int nt = 0; nt < 4; nt++) {
            const __nv_bfloat16* bp = &Wh[cn0 + nt * 8 + lq][kk + kp * 2];
            bh[nt][0] = *(const uint32_t*)bp;
            bh[nt][1] = *(const uint32_t*)(bp + 8);
            const __nv_bfloat16* bq = &Wl[cn0 + nt * 8 + lq][kk + kp * 2];
            bl[nt][0] = *(const uint32_t*)bq;
            bl[nt][1] = *(const uint32_t*)(bq + 8);
        }
#pragma unroll
        for (int mt = 0; mt < 2; mt++) {
            const __nv_bfloat16* ap = &Hh[cm0 + mt * 16 + lq][kk + kp * 2];
            uint32_t ah[4], al[4];
            ah[0] = *(const uint32_t*)ap;
            ah[1] = *(const uint32_t*)(ap + 8 * HSTRIDE);
            ah[2] = *(const uint32_t*)(ap + 8);
            ah[3] = *(const uint32_t*)(ap + 8 * HSTRIDE + 8);
            const __nv_bfloat16* aq = &Hl[cm0 + mt * 16 + lq][kk + kp * 2];
            al[0] = *(const uint32_t*)aq;
            al[1] = *(const uint32_t*)(aq + 8 * HSTRIDE);
            al[2] = *(const uint32_t*)(aq + 8);
            al[3] = *(const uint32_t*)(aq + 8 * HSTRIDE + 8);
#pragma unroll
            for (int nt = 0; nt < 4; nt++) {
                mma16816(c2[mt][nt], ah, bh[nt]);
                mma16816(c2[mt][nt], ah, bl[nt]);
                mma16816(c2[mt][nt], al, bh[nt]);
            }
        }
    }

    // writeback with classifier bias
#pragma unroll
    for (int mt = 0; mt < 2; mt++) {
        int gr0 = m0 + cm0 + mt * 16 + lq;
        int gr1 = gr0 + 8;
#pragma unroll
        for (int nt = 0; nt < 4; nt++) {
            int col = cn0 + nt * 8 + kp * 2;
            float bx = bc[col], by = bc[col + 1];
            if (gr0 < NN)
                *(float2*)(outp + (size_t)gr0 * OUTD + col) =
                    make_float2(c2[mt][nt][0] + bx, c2[mt][nt][1] + by);
            if (gr1 < NN)
                *(float2*)(outp + (size_t)gr1 * OUTD + col) =
                    make_float2(c2[mt][nt][2] + bx, c2[mt][nt][3] + by);
        }
    }
}

// ---------------- host orchestration ---------------------------------------
extern "C" void kernel_launch(void* const* d_in, const int* in_sizes, int n_in,
                              void* d_out, int out_size) {
    const float* x      = (const float*)d_in[0];
    const int*   ei     = (const int*)d_in[1];
    const int*   gei    = (const int*)d_in[2];
    const float* w_orig = (const float*)d_in[3];
    const float* b_orig = (const float*)d_in[4];
    const float* w_aug  = (const float*)d_in[5];
    const float* b_aug  = (const float*)d_in[6];
    const float* fw     = (const float*)d_in[7];
    const float* clfw   = (const float*)d_in[8];
    const float* clfb   = (const float*)d_in[9];
    float*       out    = (float*)d_out;

    float *acc0, *bufA, *bufB, *bufC, *bufD;
    cudaGetSymbolAddress((void**)&acc0, g_acc0);
    cudaGetSymbolAddress((void**)&bufA, g_bufA);
    cudaGetSymbolAddress((void**)&bufB, g_bufB);
    cudaGetSymbolAddress((void**)&bufC, g_bufC);
    cudaGetSymbolAddress((void**)&bufD, g_bufD);

    cudaFuncSetAttribute(k_gemm5_mma,
                         cudaFuncAttributeMaxDynamicSharedMemorySize, SMEM_MMA);

    const int TB = 256;
    dim3 gN((NN + TB - 1) / TB);
    dim3 gE((EE + TB - 1) / TB);
    dim3 gP((NN * 32 + TB - 1) / TB);        // pull: 1 warp/node

    for (int g = 0; g < 2; g++) {
        const int*   edges = g ? gei : ei;
        const float* W     = g ? w_aug : w_orig;
        const float* b     = g ? b_aug : b_orig;

        // CSR build (deg_init dropped: scan1 re-zeroes g_cnt each pass)
        k_deg_count<<<gE, TB>>>(edges);
        k_scan1<<<NB_SCAN, 512>>>();
        k_scan2<<<1, 256>>>();
        k_scan3<<<gN, TB>>>();
        k_fill <<<gE, TB>>>(edges);

        // hop chain: Tx1..Tx4
        k_pull<<<gP, TB>>>(x,    bufA);
        k_pull<<<gP, TB>>>(bufA, bufB);
        k_pull<<<gP, TB>>>(bufB, bufC);
        k_pull<<<gP, TB>>>(bufC, bufD);

        if (g == 0) {
            // branch 0: acc0 = relu(sum_s Tx_s @ W_s + bias_sum)
            k_gemm5_mma<<<GEMM_BLKS, TB, SMEM_MMA>>>(
                x, bufA, bufB, bufC, bufD, W, acc0, b,
                nullptr, nullptr, nullptr, nullptr, nullptr);
        } else {
            // branch 1 + fused fusion/classifier -> out
            k_gemm5_mma<<<GEMM_BLKS, TB, SMEM_MMA>>>(
                x, bufA, bufB, bufC, bufD, W, acc0 /*unused*/, b,
                acc0, fw, clfw, clfb, out);
        }
    }
}